// round 2
// baseline (speedup 1.0000x reference)
#include <cuda_runtime.h>

// Problem constants
constexpr int Bb  = 64;
constexpr int BSs = 8;
constexpr int Mm  = 512;
constexpr int Dd  = 256;
constexpr float NEG_FILL_F = -10000000000.0f;

// ---------------- scratch (static device memory; no allocations) ----------
__device__ float g_Qx[Bb * Mm * Dd];
__device__ float g_Kx[Bb * Mm * Dd];
__device__ float g_Vx[Bb * Mm * Dd];
__device__ float g_Qy[BSs * Mm * Dd];
__device__ float g_Ky[BSs * Mm * Dd];
__device__ float g_Vy[BSs * Mm * Dd];
__device__ float g_Px[Bb * Mm * Mm];    // softmax(scores_x)
__device__ float g_Py[BSs * Mm * Mm];   // softmax(scores_y)
__device__ unsigned char g_mx[Bb * Mm]; // normalized mask_x
__device__ unsigned char g_my[BSs * Mm];// normalized mask_y

// ---------------- mask normalization (dtype-agnostic) ----------------------
// Detects whether the mask buffer is byte-packed bools or int32 0/1 words:
// int32 encoding => every 4-byte word is 0 or 1. Byte encoding of random
// bools => some word > 1 with overwhelming probability. Reads stay within
// n bytes (the minimum possible buffer size).
__global__ void norm_masks_kernel(const unsigned int* __restrict__ mx_in,
                                  const unsigned int* __restrict__ my_in)
{
    const unsigned int* in = (blockIdx.x == 0) ? mx_in : my_in;
    unsigned char* out = (blockIdx.x == 0) ? g_mx : g_my;
    int n = (blockIdx.x == 0) ? Bb * Mm : BSs * Mm;

    __shared__ int s_flag;
    if (threadIdx.x == 0) s_flag = 0;
    __syncthreads();
    int words_safe = n / 4;  // fits even if buffer is only n bytes
    int local = 0;
    for (int i = threadIdx.x; i < words_safe; i += blockDim.x)
        if (in[i] > 1u) local = 1;
    if (local) atomicOr(&s_flag, 1);
    __syncthreads();
    bool byte_packed = (s_flag != 0);

    const unsigned char* inb = (const unsigned char*)in;
    for (int i = threadIdx.x; i < n; i += blockDim.x)
        out[i] = byte_packed ? (inb[i] != 0 ? 1 : 0) : (in[i] != 0u ? 1 : 0);
}

// ---------------- generic 128x128x16 NT GEMM tile (C = A * B^T) -----------
// A: [Mrows, K] row-major, B: [N, K] row-major (dot of rows)
// block: 256 threads, each computes 8x8
template<int N, int K, bool MASKED>
__device__ __forceinline__ void gemm_nt_tile(
    const float* __restrict__ A, const float* __restrict__ Bm,
    float* __restrict__ C,
    const unsigned char* __restrict__ mrow,
    const unsigned char* __restrict__ mcol)
{
    constexpr int BK = 16;
    __shared__ float As[BK][132];
    __shared__ float Bs[BK][132];

    const int tid  = threadIdx.x;
    const int tcol = tid & 15;   // 0..15
    const int trow = tid >> 4;   // 0..15
    const int row0 = blockIdx.y * 128;
    const int col0 = blockIdx.x * 128;

    float acc[8][8];
#pragma unroll
    for (int i = 0; i < 8; i++)
#pragma unroll
        for (int j = 0; j < 8; j++) acc[i][j] = 0.f;

    for (int kk = 0; kk < K; kk += BK) {
#pragma unroll
        for (int i = 0; i < 8; i++) {
            int r = trow + i * 16;
            As[tcol][r] = A[(size_t)(row0 + r) * K + (kk + tcol)];
            Bs[tcol][r] = Bm[(size_t)(col0 + r) * K + (kk + tcol)];
        }
        __syncthreads();
#pragma unroll
        for (int k = 0; k < BK; k++) {
            float4 a0 = *(const float4*)&As[k][trow * 8];
            float4 a1 = *(const float4*)&As[k][trow * 8 + 4];
            float4 b0 = *(const float4*)&Bs[k][tcol * 8];
            float4 b1 = *(const float4*)&Bs[k][tcol * 8 + 4];
            float av[8] = {a0.x, a0.y, a0.z, a0.w, a1.x, a1.y, a1.z, a1.w};
            float bv[8] = {b0.x, b0.y, b0.z, b0.w, b1.x, b1.y, b1.z, b1.w};
#pragma unroll
            for (int i = 0; i < 8; i++)
#pragma unroll
                for (int j = 0; j < 8; j++)
                    acc[i][j] = fmaf(av[i], bv[j], acc[i][j]);
        }
        __syncthreads();
    }

#pragma unroll
    for (int i = 0; i < 8; i++) {
        int r = row0 + trow * 8 + i;
        bool rm = true;
        if (MASKED) rm = (mrow[r] != 0);
        float* crow = C + (size_t)r * N + col0 + tcol * 8;
        float vals[8];
#pragma unroll
        for (int j = 0; j < 8; j++) {
            float v = acc[i][j];
            if (MASKED) {
                bool cm = (mcol[col0 + tcol * 8 + j] != 0);
                v = (rm && cm) ? v : NEG_FILL_F;
            }
            vals[j] = v;
        }
        *(float4*)&crow[0] = make_float4(vals[0], vals[1], vals[2], vals[3]);
        *(float4*)&crow[4] = make_float4(vals[4], vals[5], vals[6], vals[7]);
    }
}

// ---------------- generic 128x128x16 NN GEMM tile (C = A * B) -------------
// A: [Mrows, K] row-major, B: [K, N] row-major
template<int N, int K>
__device__ __forceinline__ void gemm_nn_tile(
    const float* __restrict__ A, const float* __restrict__ Bm,
    float* __restrict__ C)
{
    constexpr int BK = 16;
    __shared__ float As[BK][132];
    __shared__ float Bs[BK][132];

    const int tid  = threadIdx.x;
    const int tcol = tid & 15;
    const int trow = tid >> 4;
    const int row0 = blockIdx.y * 128;
    const int col0 = blockIdx.x * 128;

    float acc[8][8];
#pragma unroll
    for (int i = 0; i < 8; i++)
#pragma unroll
        for (int j = 0; j < 8; j++) acc[i][j] = 0.f;

    for (int kk = 0; kk < K; kk += BK) {
#pragma unroll
        for (int i = 0; i < 8; i++) {
            int r = trow + i * 16;
            As[tcol][r] = A[(size_t)(row0 + r) * K + (kk + tcol)];
        }
#pragma unroll
        for (int i = 0; i < 2; i++) {
            *(float4*)&Bs[trow][tcol * 8 + i * 4] =
                *(const float4*)&Bm[(size_t)(kk + trow) * N + col0 + tcol * 8 + i * 4];
        }
        __syncthreads();
#pragma unroll
        for (int k = 0; k < BK; k++) {
            float4 a0 = *(const float4*)&As[k][trow * 8];
            float4 a1 = *(const float4*)&As[k][trow * 8 + 4];
            float4 b0 = *(const float4*)&Bs[k][tcol * 8];
            float4 b1 = *(const float4*)&Bs[k][tcol * 8 + 4];
            float av[8] = {a0.x, a0.y, a0.z, a0.w, a1.x, a1.y, a1.z, a1.w};
            float bv[8] = {b0.x, b0.y, b0.z, b0.w, b1.x, b1.y, b1.z, b1.w};
#pragma unroll
            for (int i = 0; i < 8; i++)
#pragma unroll
                for (int j = 0; j < 8; j++)
                    acc[i][j] = fmaf(av[i], bv[j], acc[i][j]);
        }
        __syncthreads();
    }

#pragma unroll
    for (int i = 0; i < 8; i++) {
        int r = row0 + trow * 8 + i;
        float* crow = C + (size_t)r * N + col0 + tcol * 8;
        *(float4*)&crow[0] = make_float4(acc[i][0], acc[i][1], acc[i][2], acc[i][3]);
        *(float4*)&crow[4] = make_float4(acc[i][4], acc[i][5], acc[i][6], acc[i][7]);
    }
}

// ---------------- projections: Q/K/V for x (z=0..2) and y (z=3..5) --------
__global__ __launch_bounds__(256) void proj_kernel(
    const float* __restrict__ x, const float* __restrict__ y,
    const float* __restrict__ Wq, const float* __restrict__ Wk,
    const float* __restrict__ Wv)
{
    int z = blockIdx.z;
    const float* W = (z % 3 == 0) ? Wq : (z % 3 == 1) ? Wk : Wv;
    const float* A;
    float* C;
    if (z < 3) {
        A = x;
        C = (z == 0) ? g_Qx : (z == 1) ? g_Kx : g_Vx;
    } else {
        if (blockIdx.y >= (BSs * Mm) / 128) return;  // y has fewer rows
        A = y;
        C = (z == 3) ? g_Qy : (z == 4) ? g_Ky : g_Vy;
    }
    gemm_nt_tile<Dd, Dd, false>(A, W, C, nullptr, nullptr);
}

// ---------------- masked score GEMMs ---------------------------------------
// MODE 0: scores_x[b] = Qx[b] Kx[b]^T, mask_x/mask_x         (z = b, 64)
// MODE 1: scores_y[s] = Qy[s] Ky[s]^T, mask_y/mask_y         (z = s, 8)
// MODE 2: scores_xy[n,s] = Qx[s*8+n] Ky[s]^T, mask_x/mask_y  (z = n*8+s, 64)
template<int MODE>
__global__ __launch_bounds__(256) void scores_kernel(float* __restrict__ outbase)
{
    int z = blockIdx.z;
    const float *A, *Bm;
    const unsigned char *mr, *mc;
    float* C = outbase + (size_t)z * Mm * Mm;
    if (MODE == 0) {
        A = g_Qx + (size_t)z * Mm * Dd;
        Bm = g_Kx + (size_t)z * Mm * Dd;
        mr = g_mx + z * Mm; mc = mr;
    } else if (MODE == 1) {
        A = g_Qy + (size_t)z * Mm * Dd;
        Bm = g_Ky + (size_t)z * Mm * Dd;
        mr = g_my + z * Mm; mc = mr;
    } else {
        int n = z >> 3, s = z & 7;
        int b = s * 8 + n;
        A = g_Qx + (size_t)b * Mm * Dd;
        Bm = g_Ky + (size_t)s * Mm * Dd;
        mr = g_mx + b * Mm;
        mc = g_my + s * Mm;
    }
    gemm_nt_tile<Mm, Dd, true>(A, Bm, C, mr, mc);
}

// ---------------- row softmax (512 wide), 256 threads/block -----------------
// mode 0 -> out = g_Px, mode 1 -> out = g_Py, mode 2 -> out = outp (in-place)
__global__ __launch_bounds__(256) void softmax_kernel(
    const float* __restrict__ in, float* __restrict__ outp, int mode)
{
    float* outbase = (mode == 0) ? g_Px : (mode == 1) ? g_Py : outp;
    size_t row = blockIdx.x;
    const float* p = in + row * Mm;
    float* o = outbase + row * Mm;
    int t = threadIdx.x;

    float v0 = p[t];
    float v1 = p[t + 256];
    float m = fmaxf(v0, v1);
#pragma unroll
    for (int off = 16; off; off >>= 1)
        m = fmaxf(m, __shfl_xor_sync(0xffffffffu, m, off));
    __shared__ float smax[8], ssum[8];
    if ((t & 31) == 0) smax[t >> 5] = m;
    __syncthreads();
    float bm = smax[0];
#pragma unroll
    for (int i = 1; i < 8; i++) bm = fmaxf(bm, smax[i]);

    float e0 = __expf(v0 - bm);
    float e1 = __expf(v1 - bm);
    float s = e0 + e1;
#pragma unroll
    for (int off = 16; off; off >>= 1)
        s += __shfl_xor_sync(0xffffffffu, s, off);
    if ((t & 31) == 0) ssum[t >> 5] = s;
    __syncthreads();
    float tot = 0.f;
#pragma unroll
    for (int i = 0; i < 8; i++) tot += ssum[i];
    float inv = 1.0f / tot;
    o[t] = e0 * inv;
    o[t + 256] = e1 * inv;
}

// ---------------- context GEMMs: ctx = P @ V --------------------------------
__global__ __launch_bounds__(256) void ctx_kernel(float* __restrict__ out, int which)
{
    int b = blockIdx.z;
    const float* P = which ? g_Py : g_Px;
    const float* V = which ? g_Vy : g_Vx;
    gemm_nn_tile<Dd, Mm>(P + (size_t)b * Mm * Mm,
                         V + (size_t)b * Mm * Dd,
                         out + (size_t)b * Mm * Dd);
}

// ---------------- mask_xy as floats, y_len ----------------------------------
__global__ void mask_xy_kernel(float* __restrict__ out)
{
    int rowid = blockIdx.x;           // n*4096 + s*512 + i
    int i = rowid & 511;
    int s = (rowid >> 9) & 7;
    int n = rowid >> 12;
    bool rm = g_mx[(s * 8 + n) * Mm + i] != 0;
    float* o = out + (size_t)rowid * Mm;
    for (int j = threadIdx.x; j < Mm; j += blockDim.x)
        o[j] = rm ? (g_my[s * Mm + j] ? 1.0f : 0.0f) : 0.0f;
}

__global__ void ylen_kernel(float* __restrict__ out)
{
    int t = threadIdx.x;
    if (t >= 64) return;
    int s = t & 7;                    // out layout [n][s], value depends only on s
    int sum = 0;
    for (int j = 0; j < Mm; j++) sum += g_my[s * Mm + j] ? 1 : 0;
    out[t] = (float)sum;
}

// ---------------- launch ----------------------------------------------------
extern "C" void kernel_launch(void* const* d_in, const int* in_sizes, int n_in,
                              void* d_out, int out_size)
{
    const float* x  = (const float*)d_in[0];
    const float* y  = (const float*)d_in[1];
    const unsigned int* mask_x = (const unsigned int*)d_in[2];
    const unsigned int* mask_y = (const unsigned int*)d_in[3];
    const float* Wq = (const float*)d_in[4];
    const float* Wk = (const float*)d_in[5];
    const float* Wv = (const float*)d_in[6];

    float* out = (float*)d_out;
    // Tuple order offsets (all fp32):
    float* out_ctx_x = out;                    // 64*512*256   = 8388608
    float* out_ctx_y = out + 8388608;          // 8*512*256    = 1048576
    float* out_sx    = out + 9437184;          // 64*512*512   = 16777216
    float* out_sy    = out + 26214400;         // 8*512*512    = 2097152
    float* out_pxy   = out + 28311552;         // 8*8*512*512  = 16777216
    float* out_mxy   = out + 45088768;         // 8*8*512*512  = 16777216
    float* out_ylen  = out + 61865984;         // 8*8          = 64

    dim3 blk(256);

    // 0) normalize masks (dtype-agnostic)
    norm_masks_kernel<<<2, 1024>>>(mask_x, mask_y);

    // 1) projections (x: 32768 rows, y: 4096 rows; z = 3 weights x 2 inputs)
    proj_kernel<<<dim3(2, 256, 6), blk>>>(x, y, Wq, Wk, Wv);

    // 2) masked scores
    scores_kernel<0><<<dim3(4, 4, 64), blk>>>(out_sx);
    scores_kernel<1><<<dim3(4, 4, 8),  blk>>>(out_sy);
    scores_kernel<2><<<dim3(4, 4, 64), blk>>>(out_pxy);

    // 3) softmaxes (x,y -> scratch probs; xy in-place in output)
    softmax_kernel<<<Bb * Mm, 256>>>(out_sx, nullptr, 0);
    softmax_kernel<<<BSs * Mm, 256>>>(out_sy, nullptr, 1);
    softmax_kernel<<<Bb * Mm, 256>>>(out_pxy, out_pxy, 2);

    // 4) contexts
    ctx_kernel<<<dim3(2, 4, 64), blk>>>(out_ctx_x, 0);
    ctx_kernel<<<dim3(2, 4, 8),  blk>>>(out_ctx_y, 1);

    // 5) mask_xy + y_len
    mask_xy_kernel<<<Bb * Mm, 128>>>(out_mxy);
    ylen_kernel<<<1, 64>>>(out_ylen);
}

// round 4
// speedup vs baseline: 1.0092x; 1.0092x over previous
#include <cuda_runtime.h>
#include <cstdint>

constexpr int Bb  = 64;
constexpr int BSs = 8;
constexpr int Mm  = 512;
constexpr int Dd  = 256;
constexpr float NEG_FILL_F = -10000000000.0f;

constexpr int BK   = 16;    // k per chunk
constexpr int APAD = 20;    // floats per As row (conflict-free frag loads)
constexpr int BPAD = 20;    // NT Bs row stride
constexpr int BNNP = 136;   // NN Bs row stride (136 % 32 == 8 -> conflict-free)
constexpr int ASZ  = 128 * APAD;
constexpr int BSZ_NT = 128 * BPAD;
constexpr int BSZ_NN = BK * BNNP;

// ---------------- scratch ---------------------------------------------------
__device__ float g_Qx[Bb * Mm * Dd];
__device__ float g_Kx[Bb * Mm * Dd];
__device__ float g_Vx[Bb * Mm * Dd];
__device__ float g_Qy[BSs * Mm * Dd];
__device__ float g_Ky[BSs * Mm * Dd];
__device__ float g_Vy[BSs * Mm * Dd];
__device__ float g_Px[Bb * Mm * Mm];
__device__ float g_Py[BSs * Mm * Mm];
__device__ unsigned char g_mx[Bb * Mm];
__device__ unsigned char g_my[BSs * Mm];

// ---------------- tf32 helpers ----------------------------------------------
__device__ __forceinline__ float f_hi(float a) {
    return __uint_as_float(__float_as_uint(a) & 0xFFFFE000u);
}
__device__ __forceinline__ float tf32_rna(float a) {
    uint32_t o;
    asm("cvt.rna.tf32.f32 %0, %1;" : "=r"(o) : "f"(a));
    return __uint_as_float(o);
}
// sel: 1 = hi part (exact tf32), 2 = lo residual rounded to tf32
__device__ __forceinline__ float4 xform(float4 v, int sel) {
    if (sel == 1) {
        v.x = f_hi(v.x); v.y = f_hi(v.y); v.z = f_hi(v.z); v.w = f_hi(v.w);
    } else {
        v.x = tf32_rna(v.x - f_hi(v.x)); v.y = tf32_rna(v.y - f_hi(v.y));
        v.z = tf32_rna(v.z - f_hi(v.z)); v.w = tf32_rna(v.w - f_hi(v.w));
    }
    return v;
}

__device__ __forceinline__ void mma_tf32(float* c, const uint32_t* a, const uint32_t* b) {
    asm volatile(
        "mma.sync.aligned.m16n8k8.row.col.f32.tf32.tf32.f32 "
        "{%0,%1,%2,%3}, {%4,%5,%6,%7}, {%8,%9}, {%0,%1,%2,%3};"
        : "+f"(c[0]), "+f"(c[1]), "+f"(c[2]), "+f"(c[3])
        : "r"(a[0]), "r"(a[1]), "r"(a[2]), "r"(a[3]), "r"(b[0]), "r"(b[1]));
}

// ---------------- staging ----------------------------------------------------
// A (and NT B): 128 rows x BK cols, row-major (lda), into [row][APAD]
__device__ __forceinline__ void ldg_rowmajor(const float* __restrict__ src,
                                             int lda, int k0, float4 r[2]) {
#pragma unroll
    for (int j = 0; j < 2; j++) {
        int idx = threadIdx.x + 256 * j;
        int row = idx >> 2, q = idx & 3;
        r[j] = *(const float4*)(src + (size_t)row * lda + k0 + q * 4);
    }
}
__device__ __forceinline__ void sts_nt(float* dst, const float4 r[2], int sel) {
#pragma unroll
    for (int j = 0; j < 2; j++) {
        int idx = threadIdx.x + 256 * j;
        int row = idx >> 2, q = idx & 3;
        *(float4*)(dst + row * APAD + q * 4) = xform(r[j], sel);
    }
}
// NN B: BK rows x 128 cols (row-major ldb), into [k][BNNP]
__device__ __forceinline__ void ldg_nn(const float* __restrict__ src,
                                       int ldb, int k0, float4 r[2]) {
#pragma unroll
    for (int j = 0; j < 2; j++) {
        int idx = threadIdx.x + 256 * j;
        int row = idx >> 5, q = idx & 31;
        r[j] = *(const float4*)(src + (size_t)(k0 + row) * ldb + q * 4);
    }
}
__device__ __forceinline__ void sts_nn(float* dst, const float4 r[2], int sel) {
#pragma unroll
    for (int j = 0; j < 2; j++) {
        int idx = threadIdx.x + 256 * j;
        int row = idx >> 5, q = idx & 31;
        *(float4*)(dst + row * BNNP + q * 4) = xform(r[j], sel);
    }
}

// ---------------- per-warp compute on one BK chunk ---------------------------
// warp tile: 64x32; warps 2x4 over 128x128 CTA tile
template<bool NN_B>
__device__ __forceinline__ void compute_chunk(
    const float* __restrict__ As, const float* __restrict__ Bs,
    float (&acc)[4][4][4], int wm, int wn, int gr, int kc)
{
#pragma unroll
    for (int k8 = 0; k8 < BK; k8 += 8) {
        uint32_t a[4][4], b[4][2];
#pragma unroll
        for (int mt = 0; mt < 4; mt++) {
            const float* p = As + (wm * 64 + mt * 16 + gr) * APAD + k8 + kc;
            a[mt][0] = __float_as_uint(p[0]);
            a[mt][1] = __float_as_uint(p[8 * APAD]);
            a[mt][2] = __float_as_uint(p[4]);
            a[mt][3] = __float_as_uint(p[8 * APAD + 4]);
        }
#pragma unroll
        for (int nt = 0; nt < 4; nt++) {
            if (!NN_B) {
                const float* p = Bs + (wn * 32 + nt * 8 + gr) * BPAD + k8 + kc;
                b[nt][0] = __float_as_uint(p[0]);
                b[nt][1] = __float_as_uint(p[4]);
            } else {
                const float* p = Bs + (k8 + kc) * BNNP + wn * 32 + nt * 8 + gr;
                b[nt][0] = __float_as_uint(p[0]);
                b[nt][1] = __float_as_uint(p[4 * BNNP]);
            }
        }
#pragma unroll
        for (int mt = 0; mt < 4; mt++)
#pragma unroll
            for (int nt = 0; nt < 4; nt++)
                mma_tf32(acc[mt][nt], a[mt], b[nt]);
    }
}

// ---------------- full pipelined 3xTF32 GEMM over K --------------------------
template<bool NN_B>
__device__ __forceinline__ void gemm_run(
    const float* __restrict__ A, int lda,
    const float* __restrict__ B, int ldb, int K,
    float (&acc)[4][4][4], float* As, float* Bs, int wm, int wn, int gr, int kc)
{
    const int kdiv = K / BK;
    const int nch = 3 * kdiv;
    const int bsz = NN_B ? BSZ_NN : BSZ_NT;
    float4 rA[2], rB[2];

    ldg_rowmajor(A, lda, 0, rA);
    if (NN_B) ldg_nn(B, ldb, 0, rB); else ldg_rowmajor(B, ldb, 0, rB);
    sts_nt(As, rA, 1);
    if (NN_B) sts_nn(Bs, rB, 1); else sts_nt(Bs, rB, 1);
    __syncthreads();

    for (int c = 0; c < nch; c++) {
        int cn = c + 1;
        if (cn < nch) {
            int kcn = cn % kdiv;
            ldg_rowmajor(A, lda, kcn * BK, rA);
            if (NN_B) ldg_nn(B, ldb, kcn * BK, rB);
            else      ldg_rowmajor(B, ldb, kcn * BK, rB);
        }
        compute_chunk<NN_B>(As + (c & 1) * ASZ, Bs + (c & 1) * bsz,
                            acc, wm, wn, gr, kc);
        if (cn < nch) {
            int pass = cn / kdiv;
            int aSel = (pass == 1) ? 2 : 1;
            int bSel = (pass == 2) ? 2 : 1;
            sts_nt(As + (cn & 1) * ASZ, rA, aSel);
            if (NN_B) sts_nn(Bs + (cn & 1) * bsz, rB, bSel);
            else      sts_nt(Bs + (cn & 1) * bsz, rB, bSel);
            __syncthreads();
        }
    }
}

#define GEMM_SETUP()                                        \
    int wid = threadIdx.x >> 5, lane = threadIdx.x & 31;    \
    int wm = wid >> 2, wn = wid & 3;                        \
    int gr = lane >> 2, kc = lane & 3;                      \
    float acc[4][4][4];                                     \
    for (int i = 0; i < 4; i++)                             \
        for (int j = 0; j < 4; j++)                         \
            for (int q = 0; q < 4; q++) acc[i][j][q] = 0.f;

// ---------------- projections ------------------------------------------------
// z: 0..2 -> x {Q,K,V}, 3..5 -> y {Q,K,V}
__global__ __launch_bounds__(256, 2) void proj_kernel(
    const float* __restrict__ x, const float* __restrict__ y,
    const float* __restrict__ Wq, const float* __restrict__ Wk,
    const float* __restrict__ Wv)
{
    __shared__ float As[2 * ASZ];
    __shared__ float Bs[2 * BSZ_NT];
    int z = blockIdx.z;
    bool isY = z >= 3;
    if (isY && blockIdx.y >= 32) return;
    int mat = z % 3;
    const float* Abase = isY ? y : x;
    const float* W = (mat == 0) ? Wq : (mat == 1) ? Wk : Wv;
    int row0 = blockIdx.y * 128;
    int col0 = blockIdx.x * 128;

    GEMM_SETUP();
    gemm_run<false>(Abase + (size_t)row0 * Dd, Dd, W + (size_t)col0 * Dd, Dd, Dd,
                    acc, As, Bs, wm, wn, gr, kc);

    float* C = (mat == 0) ? (isY ? g_Qy : g_Qx)
             : (mat == 1) ? (isY ? g_Ky : g_Kx)
                          : (isY ? g_Vy : g_Vx);
#pragma unroll
    for (int mt = 0; mt < 4; mt++) {
        int r = row0 + wm * 64 + mt * 16 + gr;
#pragma unroll
        for (int nt = 0; nt < 4; nt++) {
            int c = col0 + wn * 32 + nt * 8 + kc * 2;
            *(float2*)(C + (size_t)r * Dd + c) = make_float2(acc[mt][nt][0], acc[mt][nt][1]);
            *(float2*)(C + (size_t)(r + 8) * Dd + c) = make_float2(acc[mt][nt][2], acc[mt][nt][3]);
        }
    }
}

// ---------------- masked score GEMMs ------------------------------------------
template<int MODE>
__global__ __launch_bounds__(256, 2) void scores_kernel(float* __restrict__ outbase)
{
    __shared__ float As[2 * ASZ];
    __shared__ float Bs[2 * BSZ_NT];
    int zb = blockIdx.z;
    const float *A, *Bp;
    const unsigned char *mr, *mc;
    float* C = outbase + (size_t)zb * Mm * Mm;
    if (MODE == 0) {
        A = g_Qx + (size_t)zb * Mm * Dd; Bp = g_Kx + (size_t)zb * Mm * Dd;
        mr = g_mx + zb * Mm; mc = mr;
    } else if (MODE == 1) {
        A = g_Qy + (size_t)zb * Mm * Dd; Bp = g_Ky + (size_t)zb * Mm * Dd;
        mr = g_my + zb * Mm; mc = mr;
    } else {
        int n = zb >> 3, s = zb & 7, b = s * 8 + n;
        A = g_Qx + (size_t)b * Mm * Dd; Bp = g_Ky + (size_t)s * Mm * Dd;
        mr = g_mx + b * Mm; mc = g_my + s * Mm;
    }
    int row0 = blockIdx.y * 128, col0 = blockIdx.x * 128;

    GEMM_SETUP();
    gemm_run<false>(A + (size_t)row0 * Dd, Dd, Bp + (size_t)col0 * Dd, Dd, Dd,
                    acc, As, Bs, wm, wn, gr, kc);

#pragma unroll
    for (int mt = 0; mt < 4; mt++) {
        int r = row0 + wm * 64 + mt * 16 + gr;
        bool rm0 = mr[r] != 0, rm1 = mr[r + 8] != 0;
#pragma unroll
        for (int nt = 0; nt < 4; nt++) {
            int c = col0 + wn * 32 + nt * 8 + kc * 2;
            bool c0 = mc[c] != 0, c1 = mc[c + 1] != 0;
            float2 v0, v1;
            v0.x = (rm0 && c0) ? acc[mt][nt][0] : NEG_FILL_F;
            v0.y = (rm0 && c1) ? acc[mt][nt][1] : NEG_FILL_F;
            v1.x = (rm1 && c0) ? acc[mt][nt][2] : NEG_FILL_F;
            v1.y = (rm1 && c1) ? acc[mt][nt][3] : NEG_FILL_F;
            *(float2*)(C + (size_t)r * Mm + c) = v0;
            *(float2*)(C + (size_t)(r + 8) * Mm + c) = v1;
        }
    }
}

// ---------------- context GEMMs: ctx = P @ V (NN) ------------------------------
__global__ __launch_bounds__(256, 2) void ctx_kernel(float* __restrict__ out, int which)
{
    __shared__ float As[2 * ASZ];
    __shared__ float Bs[2 * BSZ_NN];
    int b = blockIdx.z;
    const float* P = (which ? g_Py : g_Px) + (size_t)b * Mm * Mm;
    const float* V = (which ? g_Vy : g_Vx) + (size_t)b * Mm * Dd;
    int row0 = blockIdx.y * 128, col0 = blockIdx.x * 128;

    GEMM_SETUP();
    gemm_run<true>(P + (size_t)row0 * Mm, Mm, V + col0, Dd, Mm,
                   acc, As, Bs, wm, wn, gr, kc);

    float* O = out + (size_t)b * Mm * Dd;
#pragma unroll
    for (int mt = 0; mt < 4; mt++) {
        int r = row0 + wm * 64 + mt * 16 + gr;
#pragma unroll
        for (int nt = 0; nt < 4; nt++) {
            int c = col0 + wn * 32 + nt * 8 + kc * 2;
            *(float2*)(O + (size_t)r * Dd + c) = make_float2(acc[mt][nt][0], acc[mt][nt][1]);
            *(float2*)(O + (size_t)(r + 8) * Dd + c) = make_float2(acc[mt][nt][2], acc[mt][nt][3]);
        }
    }
}

// ---------------- mask normalization (dtype-agnostic) --------------------------
__global__ void norm_masks_kernel(const unsigned int* __restrict__ mx_in,
                                  const unsigned int* __restrict__ my_in)
{
    const unsigned int* in = (blockIdx.x == 0) ? mx_in : my_in;
    unsigned char* out = (blockIdx.x == 0) ? g_mx : g_my;
    int n = (blockIdx.x == 0) ? Bb * Mm : BSs * Mm;

    __shared__ int s_flag;
    if (threadIdx.x == 0) s_flag = 0;
    __syncthreads();
    int local = 0;
    for (int i = threadIdx.x; i < n / 4; i += blockDim.x)
        if (in[i] > 1u) local = 1;
    if (local) atomicOr(&s_flag, 1);
    __syncthreads();
    bool byte_packed = (s_flag != 0);

    const unsigned char* inb = (const unsigned char*)in;
    for (int i = threadIdx.x; i < n; i += blockDim.x)
        out[i] = byte_packed ? (inb[i] != 0 ? 1 : 0) : (in[i] != 0u ? 1 : 0);
}

// ---------------- row softmax (512 wide) ----------------------------------------
__global__ __launch_bounds__(256) void softmax_kernel(
    const float* __restrict__ in, float* __restrict__ outp, int mode)
{
    float* outbase = (mode == 0) ? g_Px : (mode == 1) ? g_Py : outp;
    size_t row = blockIdx.x;
    const float* p = in + row * Mm;
    float* o = outbase + row * Mm;
    int t = threadIdx.x;

    float v0 = p[t];
    float v1 = p[t + 256];
    float m = fmaxf(v0, v1);
#pragma unroll
    for (int off = 16; off; off >>= 1)
        m = fmaxf(m, __shfl_xor_sync(0xffffffffu, m, off));
    __shared__ float smax[8], ssum[8];
    if ((t & 31) == 0) smax[t >> 5] = m;
    __syncthreads();
    float bm = smax[0];
#pragma unroll
    for (int i = 1; i < 8; i++) bm = fmaxf(bm, smax[i]);

    float e0 = __expf(v0 - bm);
    float e1 = __expf(v1 - bm);
    float s = e0 + e1;
#pragma unroll
    for (int off = 16; off; off >>= 1)
        s += __shfl_xor_sync(0xffffffffu, s, off);
    if ((t & 31) == 0) ssum[t >> 5] = s;
    __syncthreads();
    float tot = 0.f;
#pragma unroll
    for (int i = 0; i < 8; i++) tot += ssum[i];
    float inv = 1.0f / tot;
    o[t] = e0 * inv;
    o[t + 256] = e1 * inv;
}

// ---------------- mask_xy as floats, y_len ---------------------------------------
__global__ void mask_xy_kernel(float* __restrict__ out)
{
    int rowid = blockIdx.x;
    int i = rowid & 511;
    int s = (rowid >> 9) & 7;
    int n = rowid >> 12;
    bool rm = g_mx[(s * 8 + n) * Mm + i] != 0;
    float* o = out + (size_t)rowid * Mm;
    for (int j = threadIdx.x; j < Mm; j += blockDim.x)
        o[j] = rm ? (g_my[s * Mm + j] ? 1.0f : 0.0f) : 0.0f;
}

__global__ void ylen_kernel(float* __restrict__ out)
{
    int t = threadIdx.x;
    if (t >= 64) return;
    int s = t & 7;
    int sum = 0;
    for (int j = 0; j < Mm; j++) sum += g_my[s * Mm + j] ? 1 : 0;
    out[t] = (float)sum;
}

// ---------------- launch ----------------------------------------------------------
extern "C" void kernel_launch(void* const* d_in, const int* in_sizes, int n_in,
                              void* d_out, int out_size)
{
    const float* x  = (const float*)d_in[0];
    const float* y  = (const float*)d_in[1];
    const unsigned int* mask_x = (const unsigned int*)d_in[2];
    const unsigned int* mask_y = (const unsigned int*)d_in[3];
    const float* Wq = (const float*)d_in[4];
    const float* Wk = (const float*)d_in[5];
    const float* Wv = (const float*)d_in[6];

    float* out = (float*)d_out;
    float* out_ctx_x = out;                    // 64*512*256
    float* out_ctx_y = out + 8388608;          // 8*512*256
    float* out_sx    = out + 9437184;          // 64*512*512
    float* out_sy    = out + 26214400;         // 8*512*512
    float* out_pxy   = out + 28311552;         // 64*512*512
    float* out_mxy   = out + 45088768;         // 64*512*512
    float* out_ylen  = out + 61865984;         // 64

    dim3 blk(256);

    norm_masks_kernel<<<2, 1024>>>(mask_x, mask_y);

    proj_kernel<<<dim3(2, 256, 6), blk>>>(x, y, Wq, Wk, Wv);

    scores_kernel<0><<<dim3(4, 4, 64), blk>>>(out_sx);
    scores_kernel<1><<<dim3(4, 4, 8),  blk>>>(out_sy);
    scores_kernel<2><<<dim3(4, 4, 64), blk>>>(out_pxy);

    softmax_kernel<<<Bb * Mm, 256>>>(out_sx, nullptr, 0);
    softmax_kernel<<<BSs * Mm, 256>>>(out_sy, nullptr, 1);
    softmax_kernel<<<Bb * Mm, 256>>>(out_pxy, out_pxy, 2);

    ctx_kernel<<<dim3(2, 4, 64), blk>>>(out_ctx_x, 0);
    ctx_kernel<<<dim3(2, 4, 8),  blk>>>(out_ctx_y, 1);

    mask_xy_kernel<<<Bb * Mm, 128>>>(out_mxy);
    ylen_kernel<<<1, 64>>>(out_ylen);
}

// round 5
// speedup vs baseline: 1.2003x; 1.1894x over previous
#include <cuda_runtime.h>
#include <cstdint>

constexpr int Bb  = 64;
constexpr int BSs = 8;
constexpr int Mm  = 512;
constexpr int Dd  = 256;
constexpr float NEG_FILL_F = -10000000000.0f;

constexpr int BK    = 16;
constexpr int APAD  = 20;     // floats per 16-float row in smem (conflict-free)
constexpr int BNNP  = 136;    // NN B row stride
constexpr int DEPTH = 4;
constexpr int ASTG    = 256 * APAD;   // 5120 floats per A stage
constexpr int BSTG_NT = 128 * APAD;   // 2560
constexpr int BSTG_NN = BK * BNNP;    // 2176
constexpr int DSMEM_NT = DEPTH * (ASTG + BSTG_NT) * 4;   // 122880 B
constexpr int DSMEM_NN = DEPTH * (ASTG + BSTG_NN) * 4;   // 116736 B

// ---------------- scratch (static device memory) ----------------------------
__device__ float g_x2[(size_t)Bb * Mm * 2 * Dd];    // x split [hi|lo], width 512
__device__ float g_y2[(size_t)BSs * Mm * 2 * Dd];
__device__ float g_W2[3][(size_t)Dd * 2 * Dd];      // Wq/Wk/Wv split
__device__ float g_Qx2[(size_t)Bb * Mm * 2 * Dd];   // Q split, width 512
__device__ float g_Kx2[(size_t)Bb * Mm * 2 * Dd];
__device__ float g_Qy2[(size_t)BSs * Mm * 2 * Dd];
__device__ float g_Ky2[(size_t)BSs * Mm * 2 * Dd];
__device__ float g_Vx[(size_t)Bb * Mm * Dd];        // V, rna-rounded tf32
__device__ float g_Vy[(size_t)BSs * Mm * Dd];
__device__ float g_Px[(size_t)Bb * Mm * Mm];        // probs, rna-rounded tf32
__device__ float g_Py[(size_t)BSs * Mm * Mm];
__device__ unsigned char g_mx[Bb * Mm];
__device__ unsigned char g_my[BSs * Mm];

// ---------------- helpers ----------------------------------------------------
__device__ __forceinline__ float f_hi(float a) {
    return __uint_as_float(__float_as_uint(a) & 0xFFFFE000u);
}
__device__ __forceinline__ float tf32_rna(float a) {
    uint32_t o;
    asm("cvt.rna.tf32.f32 %0, %1;" : "=r"(o) : "f"(a));
    return __uint_as_float(o);
}
__device__ __forceinline__ uint32_t smem_u32(const void* p) {
    uint32_t a;
    asm("{ .reg .u64 t; cvta.to.shared.u64 t, %1; cvt.u32.u64 %0, t; }"
        : "=r"(a) : "l"(p));
    return a;
}
__device__ __forceinline__ void cpa16(uint32_t dst, const float* src) {
    asm volatile("cp.async.cg.shared.global [%0], [%1], 16;"
                 :: "r"(dst), "l"(src) : "memory");
}
__device__ __forceinline__ void mma_tf32(float* c, const uint32_t* a, const uint32_t* b) {
    asm volatile(
        "mma.sync.aligned.m16n8k8.row.col.f32.tf32.tf32.f32 "
        "{%0,%1,%2,%3}, {%4,%5,%6,%7}, {%8,%9}, {%0,%1,%2,%3};"
        : "+f"(c[0]), "+f"(c[1]), "+f"(c[2]), "+f"(c[3])
        : "r"(a[0]), "r"(a[1]), "r"(a[2]), "r"(a[3]), "r"(b[0]), "r"(b[1]));
}

// ---------------- cp.async stage issue ----------------------------------------
// chunk c -> pass = c/kdiv (3xTF32: (hi,hi),(lo,hi),(hi,lo)); offsets into
// [hi|lo]-concat arrays of width 2K. For NPASS=1 arrays are plain width-K.
template<bool NN_B>
__device__ __forceinline__ void issue_stage(
    const float* __restrict__ A, int lda,
    const float* __restrict__ B, int ldb, int K, int kdiv,
    int c, int nch, uint32_t asb, uint32_t bsb)
{
    if (c < nch) {
        int pass = c / kdiv;
        int kc = c - pass * kdiv;
        int acol = kc * BK + ((pass == 1) ? K : 0);
        int bcol = kc * BK + ((pass == 2) ? K : 0);
        int buf = c & (DEPTH - 1);
        uint32_t ad = asb + buf * (ASTG * 4);
        uint32_t bd = bsb + buf * ((NN_B ? BSTG_NN : BSTG_NT) * 4);
#pragma unroll
        for (int j = 0; j < 4; j++) {             // A: 256 rows x 4 segs
            int idx = threadIdx.x + 256 * j;
            int row = idx >> 2, seg = idx & 3;
            cpa16(ad + (row * APAD + seg * 4) * 4,
                  A + (size_t)row * lda + acol + seg * 4);
        }
        if (!NN_B) {
#pragma unroll
            for (int j = 0; j < 2; j++) {         // B NT: 128 rows x 4 segs
                int idx = threadIdx.x + 256 * j;
                int row = idx >> 2, seg = idx & 3;
                cpa16(bd + (row * APAD + seg * 4) * 4,
                      B + (size_t)row * ldb + bcol + seg * 4);
            }
        } else {
#pragma unroll
            for (int j = 0; j < 2; j++) {         // B NN: 16 k-rows x 32 segs
                int idx = threadIdx.x + 256 * j;
                int row = idx >> 5, seg = idx & 31;
                cpa16(bd + (row * BNNP + seg * 4) * 4,
                      B + (size_t)(bcol + row) * ldb + seg * 4);
            }
        }
    }
    asm volatile("cp.async.commit_group;" ::: "memory");
}

// ---------------- per-warp compute on one BK chunk -----------------------------
// CTA tile 256x128; 8 warps as 4(m) x 2(n); warp tile 64x64 (4x8 mma grid)
template<bool NN_B>
__device__ __forceinline__ void compute_chunk(
    const float* __restrict__ As, const float* __restrict__ Bs,
    float (&acc)[4][8][4], int wm, int wn, int gr, int kc)
{
#pragma unroll
    for (int k8 = 0; k8 < BK; k8 += 8) {
        uint32_t a[4][4], b[8][2];
#pragma unroll
        for (int mt = 0; mt < 4; mt++) {
            const float* p = As + (wm * 64 + mt * 16 + gr) * APAD + k8 + kc;
            a[mt][0] = __float_as_uint(p[0]);
            a[mt][1] = __float_as_uint(p[8 * APAD]);
            a[mt][2] = __float_as_uint(p[4]);
            a[mt][3] = __float_as_uint(p[8 * APAD + 4]);
        }
#pragma unroll
        for (int nt = 0; nt < 8; nt++) {
            if (!NN_B) {
                const float* p = Bs + (wn * 64 + nt * 8 + gr) * APAD + k8 + kc;
                b[nt][0] = __float_as_uint(p[0]);
                b[nt][1] = __float_as_uint(p[4]);
            } else {
                const float* p = Bs + (k8 + kc) * BNNP + wn * 64 + nt * 8 + gr;
                b[nt][0] = __float_as_uint(p[0]);
                b[nt][1] = __float_as_uint(p[4 * BNNP]);
            }
        }
#pragma unroll
        for (int mt = 0; mt < 4; mt++)
#pragma unroll
            for (int nt = 0; nt < 8; nt++)
                mma_tf32(acc[mt][nt], a[mt], b[nt]);
    }
}

// ---------------- pipelined GEMM over K ----------------------------------------
template<bool NN_B, int NPASS>
__device__ __forceinline__ void gemm_cp(
    const float* __restrict__ A, int lda,
    const float* __restrict__ B, int ldb, int K,
    float (&acc)[4][8][4], float* As, float* Bs, int wm, int wn, int gr, int kc)
{
    const int kdiv = K / BK;
    const int nch = NPASS * kdiv;
    uint32_t asb = smem_u32(As), bsb = smem_u32(Bs);
#pragma unroll
    for (int s = 0; s < DEPTH - 1; s++)
        issue_stage<NN_B>(A, lda, B, ldb, K, kdiv, s, nch, asb, bsb);
    for (int c = 0; c < nch; c++) {
        asm volatile("cp.async.wait_group 2;" ::: "memory");
        __syncthreads();
        int buf = c & (DEPTH - 1);
        compute_chunk<NN_B>(As + buf * ASTG,
                            Bs + buf * (NN_B ? BSTG_NN : BSTG_NT),
                            acc, wm, wn, gr, kc);
        issue_stage<NN_B>(A, lda, B, ldb, K, kdiv, c + DEPTH - 1, nch, asb, bsb);
    }
}

#define GEMM_SETUP()                                        \
    extern __shared__ float smem[];                         \
    float* As = smem;                                       \
    float* Bs = smem + DEPTH * ASTG;                        \
    int wid = threadIdx.x >> 5, lane = threadIdx.x & 31;    \
    int wm = wid >> 1, wn = wid & 1;                        \
    int gr = lane >> 2, kc = lane & 3;                      \
    float acc[4][8][4];                                     \
    _Pragma("unroll") for (int i = 0; i < 4; i++)           \
    _Pragma("unroll") for (int j = 0; j < 8; j++)           \
    _Pragma("unroll") for (int q = 0; q < 4; q++) acc[i][j][q] = 0.f;

// ---------------- split kernel: a -> [hi | lo_rna] concat along K --------------
__global__ void split_kernel(const float* __restrict__ src,
                             float* __restrict__ dst, int rows, int K)
{
    size_t i = (size_t)blockIdx.x * blockDim.x + threadIdx.x;
    if (i >= (size_t)rows * K) return;
    int r = (int)(i / K), c = (int)(i % K);
    float v = src[i];
    float h = f_hi(v);
    dst[(size_t)r * 2 * K + c] = h;
    dst[(size_t)r * 2 * K + K + c] = tf32_rna(v - h);
}

// ---------------- projections (3xTF32): z = 0..2 x{Q,K,V}, 3..5 y{Q,K,V} -------
__global__ __launch_bounds__(256, 1) void proj_kernel()
{
    int z = blockIdx.z;
    bool isY = z >= 3;
    if (isY && blockIdx.y >= 16) return;
    int mat = z % 3;
    const float* A2 = isY ? g_y2 : g_x2;
    const float* B2 = g_W2[mat];
    int row0 = blockIdx.y * 256, col0 = blockIdx.x * 128;

    GEMM_SETUP();
    gemm_cp<false, 3>(A2 + (size_t)row0 * (2 * Dd), 2 * Dd,
                      B2 + (size_t)col0 * (2 * Dd), 2 * Dd, Dd,
                      acc, As, Bs, wm, wn, gr, kc);

    if (mat < 2) {
        float* Q2 = (mat == 0) ? (isY ? g_Qy2 : g_Qx2) : (isY ? g_Ky2 : g_Kx2);
#pragma unroll
        for (int mt = 0; mt < 4; mt++) {
            int r = row0 + wm * 64 + mt * 16 + gr;
#pragma unroll
            for (int nt = 0; nt < 8; nt++) {
                int c = col0 + wn * 64 + nt * 8 + kc * 2;
#pragma unroll
                for (int h2 = 0; h2 < 2; h2++) {
                    int rr = r + h2 * 8;
                    float v0 = acc[mt][nt][h2 * 2], v1 = acc[mt][nt][h2 * 2 + 1];
                    float h0 = f_hi(v0), h1 = f_hi(v1);
                    *(float2*)(Q2 + (size_t)rr * 512 + c) = make_float2(h0, h1);
                    *(float2*)(Q2 + (size_t)rr * 512 + 256 + c) =
                        make_float2(tf32_rna(v0 - h0), tf32_rna(v1 - h1));
                }
            }
        }
    } else {
        float* V = isY ? g_Vy : g_Vx;
#pragma unroll
        for (int mt = 0; mt < 4; mt++) {
            int r = row0 + wm * 64 + mt * 16 + gr;
#pragma unroll
            for (int nt = 0; nt < 8; nt++) {
                int c = col0 + wn * 64 + nt * 8 + kc * 2;
#pragma unroll
                for (int h2 = 0; h2 < 2; h2++) {
                    int rr = r + h2 * 8;
                    *(float2*)(V + (size_t)rr * Dd + c) =
                        make_float2(tf32_rna(acc[mt][nt][h2 * 2]),
                                    tf32_rna(acc[mt][nt][h2 * 2 + 1]));
                }
            }
        }
    }
}

// ---------------- masked score GEMMs (3xTF32 on pre-split Q/K) ------------------
template<int MODE>
__global__ __launch_bounds__(256, 1) void scores_kernel(float* __restrict__ outbase)
{
    int zb = blockIdx.z;
    const float *A, *Bp;
    const unsigned char *mr, *mc;
    float* C = outbase + (size_t)zb * Mm * Mm;
    if (MODE == 0) {
        A = g_Qx2 + (size_t)zb * Mm * 512; Bp = g_Kx2 + (size_t)zb * Mm * 512;
        mr = g_mx + zb * Mm; mc = mr;
    } else if (MODE == 1) {
        A = g_Qy2 + (size_t)zb * Mm * 512; Bp = g_Ky2 + (size_t)zb * Mm * 512;
        mr = g_my + zb * Mm; mc = mr;
    } else {
        int n = zb >> 3, s = zb & 7, b = s * 8 + n;
        A = g_Qx2 + (size_t)b * Mm * 512; Bp = g_Ky2 + (size_t)s * Mm * 512;
        mr = g_mx + b * Mm; mc = g_my + s * Mm;
    }
    int row0 = blockIdx.y * 256, col0 = blockIdx.x * 128;

    GEMM_SETUP();
    gemm_cp<false, 3>(A + (size_t)row0 * 512, 512,
                      Bp + (size_t)col0 * 512, 512, Dd,
                      acc, As, Bs, wm, wn, gr, kc);

#pragma unroll
    for (int mt = 0; mt < 4; mt++) {
        int r = row0 + wm * 64 + mt * 16 + gr;
        bool rm0 = mr[r] != 0, rm1 = mr[r + 8] != 0;
#pragma unroll
        for (int nt = 0; nt < 8; nt++) {
            int c = col0 + wn * 64 + nt * 8 + kc * 2;
            bool c0 = mc[c] != 0, c1 = mc[c + 1] != 0;
            float2 v0, v1;
            v0.x = (rm0 && c0) ? acc[mt][nt][0] : NEG_FILL_F;
            v0.y = (rm0 && c1) ? acc[mt][nt][1] : NEG_FILL_F;
            v1.x = (rm1 && c0) ? acc[mt][nt][2] : NEG_FILL_F;
            v1.y = (rm1 && c1) ? acc[mt][nt][3] : NEG_FILL_F;
            *(float2*)(C + (size_t)r * Mm + c) = v0;
            *(float2*)(C + (size_t)(r + 8) * Mm + c) = v1;
        }
    }
}

// ---------------- context GEMMs: ctx = P @ V (NN, 1-pass tf32) ------------------
__global__ __launch_bounds__(256, 1) void ctx_kernel(float* __restrict__ out, int which)
{
    int b = blockIdx.z;
    const float* P = (which ? g_Py : g_Px) + (size_t)b * Mm * Mm;
    const float* V = (which ? g_Vy : g_Vx) + (size_t)b * Mm * Dd;
    int row0 = blockIdx.y * 256, col0 = blockIdx.x * 128;

    GEMM_SETUP();
    gemm_cp<true, 1>(P + (size_t)row0 * Mm, Mm, V + col0, Dd, Mm,
                     acc, As, Bs, wm, wn, gr, kc);

    float* O = out + (size_t)b * Mm * Dd;
#pragma unroll
    for (int mt = 0; mt < 4; mt++) {
        int r = row0 + wm * 64 + mt * 16 + gr;
#pragma unroll
        for (int nt = 0; nt < 8; nt++) {
            int c = col0 + wn * 64 + nt * 8 + kc * 2;
            *(float2*)(O + (size_t)r * Dd + c) =
                make_float2(acc[mt][nt][0], acc[mt][nt][1]);
            *(float2*)(O + (size_t)(r + 8) * Dd + c) =
                make_float2(acc[mt][nt][2], acc[mt][nt][3]);
        }
    }
}

// ---------------- mask normalization (dtype-agnostic) ---------------------------
__global__ void norm_masks_kernel(const unsigned int* __restrict__ mx_in,
                                  const unsigned int* __restrict__ my_in)
{
    const unsigned int* in = (blockIdx.x == 0) ? mx_in : my_in;
    unsigned char* out = (blockIdx.x == 0) ? g_mx : g_my;
    int n = (blockIdx.x == 0) ? Bb * Mm : BSs * Mm;

    __shared__ int s_flag;
    if (threadIdx.x == 0) s_flag = 0;
    __syncthreads();
    int local = 0;
    for (int i = threadIdx.x; i < n / 4; i += blockDim.x)
        if (in[i] > 1u) local = 1;
    if (local) atomicOr(&s_flag, 1);
    __syncthreads();
    bool byte_packed = (s_flag != 0);

    const unsigned char* inb = (const unsigned char*)in;
    for (int i = threadIdx.x; i < n; i += blockDim.x)
        out[i] = byte_packed ? (inb[i] != 0 ? 1 : 0) : (in[i] != 0u ? 1 : 0);
}

// ---------------- row softmax (512 wide) -----------------------------------------
// mode 0/1: write rna-rounded tf32 probs to g_Px/g_Py (consumed by ctx MMA).
// mode 2: write raw fp32 probs in place (output).
__global__ __launch_bounds__(256) void softmax_kernel(
    const float* __restrict__ in, float* __restrict__ outp, int mode)
{
    float* outbase = (mode == 0) ? g_Px : (mode == 1) ? g_Py : outp;
    size_t row = blockIdx.x;
    const float* p = in + row * Mm;
    float* o = outbase + row * Mm;
    int t = threadIdx.x;

    float v0 = p[t];
    float v1 = p[t + 256];
    float m = fmaxf(v0, v1);
#pragma unroll
    for (int off = 16; off; off >>= 1)
        m = fmaxf(m, __shfl_xor_sync(0xffffffffu, m, off));
    __shared__ float smax[8], ssum[8];
    if ((t & 31) == 0) smax[t >> 5] = m;
    __syncthreads();
    float bm = smax[0];
#pragma unroll
    for (int i = 1; i < 8; i++) bm = fmaxf(bm, smax[i]);

    float e0 = __expf(v0 - bm);
    float e1 = __expf(v1 - bm);
    float s = e0 + e1;
#pragma unroll
    for (int off = 16; off; off >>= 1)
        s += __shfl_xor_sync(0xffffffffu, s, off);
    if ((t & 31) == 0) ssum[t >> 5] = s;
    __syncthreads();
    float tot = 0.f;
#pragma unroll
    for (int i = 0; i < 8; i++) tot += ssum[i];
    float inv = 1.0f / tot;
    if (mode < 2) {
        o[t] = tf32_rna(e0 * inv);
        o[t + 256] = tf32_rna(e1 * inv);
    } else {
        o[t] = e0 * inv;
        o[t + 256] = e1 * inv;
    }
}

// ---------------- mask_xy as floats, y_len ----------------------------------------
__global__ void mask_xy_kernel(float* __restrict__ out)
{
    int rowid = blockIdx.x;
    int i = rowid & 511;
    int s = (rowid >> 9) & 7;
    int n = rowid >> 12;
    bool rm = g_mx[(s * 8 + n) * Mm + i] != 0;
    float* o = out + (size_t)rowid * Mm;
    for (int j = threadIdx.x; j < Mm; j += blockDim.x)
        o[j] = rm ? (g_my[s * Mm + j] ? 1.0f : 0.0f) : 0.0f;
}

__global__ void ylen_kernel(float* __restrict__ out)
{
    int t = threadIdx.x;
    if (t >= 64) return;
    int s = t & 7;
    int sum = 0;
    for (int j = 0; j < Mm; j++) sum += g_my[s * Mm + j] ? 1 : 0;
    out[t] = (float)sum;
}

// ---------------- launch ------------------------------------------------------------
extern "C" void kernel_launch(void* const* d_in, const int* in_sizes, int n_in,
                              void* d_out, int out_size)
{
    const float* x  = (const float*)d_in[0];
    const float* y  = (const float*)d_in[1];
    const unsigned int* mask_x = (const unsigned int*)d_in[2];
    const unsigned int* mask_y = (const unsigned int*)d_in[3];
    const float* Wq = (const float*)d_in[4];
    const float* Wk = (const float*)d_in[5];
    const float* Wv = (const float*)d_in[6];

    float* out = (float*)d_out;
    float* out_ctx_x = out;                    // 64*512*256
    float* out_ctx_y = out + 8388608;          // 8*512*256
    float* out_sx    = out + 9437184;          // 64*512*512
    float* out_sy    = out + 26214400;         // 8*512*512
    float* out_pxy   = out + 28311552;         // 64*512*512
    float* out_mxy   = out + 45088768;         // 64*512*512
    float* out_ylen  = out + 61865984;         // 64

    static bool attrs_set = false;
    cudaFuncSetAttribute(proj_kernel, cudaFuncAttributeMaxDynamicSharedMemorySize, DSMEM_NT);
    cudaFuncSetAttribute(scores_kernel<0>, cudaFuncAttributeMaxDynamicSharedMemorySize, DSMEM_NT);
    cudaFuncSetAttribute(scores_kernel<1>, cudaFuncAttributeMaxDynamicSharedMemorySize, DSMEM_NT);
    cudaFuncSetAttribute(scores_kernel<2>, cudaFuncAttributeMaxDynamicSharedMemorySize, DSMEM_NT);
    cudaFuncSetAttribute(ctx_kernel, cudaFuncAttributeMaxDynamicSharedMemorySize, DSMEM_NN);
    (void)attrs_set;

    dim3 blk(256);

    // 0) mask normalize + input/weight splits
    norm_masks_kernel<<<2, 1024>>>(mask_x, mask_y);
    {
        float* dx2;  cudaGetSymbolAddress((void**)&dx2, g_x2);
        float* dy2;  cudaGetSymbolAddress((void**)&dy2, g_y2);
        float* dW2;  cudaGetSymbolAddress((void**)&dW2, g_W2);
        split_kernel<<<(Bb * Mm * Dd + 255) / 256, 256>>>(x, dx2, Bb * Mm, Dd);
        split_kernel<<<(BSs * Mm * Dd + 255) / 256, 256>>>(y, dy2, BSs * Mm, Dd);
        split_kernel<<<(Dd * Dd + 255) / 256, 256>>>(Wq, dW2, Dd, Dd);
        split_kernel<<<(Dd * Dd + 255) / 256, 256>>>(Wk, dW2 + (size_t)Dd * 2 * Dd, Dd, Dd);
        split_kernel<<<(Dd * Dd + 255) / 256, 256>>>(Wv, dW2 + (size_t)2 * Dd * 2 * Dd, Dd, Dd);
    }

    // 1) projections
    proj_kernel<<<dim3(2, 128, 6), blk, DSMEM_NT>>>();

    // 2) masked scores
    scores_kernel<0><<<dim3(4, 2, 64), blk, DSMEM_NT>>>(out_sx);
    scores_kernel<1><<<dim3(4, 2, 8),  blk, DSMEM_NT>>>(out_sy);
    scores_kernel<2><<<dim3(4, 2, 64), blk, DSMEM_NT>>>(out_pxy);

    // 3) softmaxes
    softmax_kernel<<<Bb * Mm, 256>>>(out_sx, nullptr, 0);
    softmax_kernel<<<BSs * Mm, 256>>>(out_sy, nullptr, 1);
    softmax_kernel<<<Bb * Mm, 256>>>(out_pxy, out_pxy, 2);

    // 4) contexts
    ctx_kernel<<<dim3(2, 2, 64), blk, DSMEM_NN>>>(out_ctx_x, 0);
    ctx_kernel<<<dim3(2, 2, 8),  blk, DSMEM_NN>>>(out_ctx_y, 1);

    // 5) mask_xy + y_len
    mask_xy_kernel<<<Bb * Mm, 128>>>(out_mxy);
    ylen_kernel<<<1, 64>>>(out_ylen);
}

// round 6
// speedup vs baseline: 1.2675x; 1.0560x over previous
#include <cuda_runtime.h>
#include <cstdint>

constexpr int Bb  = 64;
constexpr int BSs = 8;
constexpr int Mm  = 512;
constexpr int Dd  = 256;
constexpr float NEG_FILL_F = -10000000000.0f;

constexpr int BK    = 16;
constexpr int BNNP  = 136;              // NN B row stride (ctx V path)
constexpr int DEPTH = 4;
constexpr int ASTG    = 256 * BK;       // 4096 floats per A stage (16KB)
constexpr int BSTG_NT = 128 * BK;       // 2048 floats
constexpr int BSTG_NN = BK * BNNP;      // 2176 floats
constexpr int DSMEM_NT = DEPTH * (ASTG + BSTG_NT) * 4;   // 98304 B
constexpr int DSMEM_NN = DEPTH * (ASTG + BSTG_NN) * 4;   // 100352 B

// ---------------- scratch (static device memory) ----------------------------
__device__ float g_x2[(size_t)Bb * Mm * 2 * Dd];    // x split [hi|lo], k-permuted
__device__ float g_y2[(size_t)BSs * Mm * 2 * Dd];
__device__ float g_W2[3][(size_t)Dd * 2 * Dd];      // W split; q/k rows permuted too
__device__ float g_Qx2[(size_t)Bb * Mm * 2 * Dd];   // Q split, k-permuted
__device__ float g_Kx2[(size_t)Bb * Mm * 2 * Dd];
__device__ float g_Qy2[(size_t)BSs * Mm * 2 * Dd];
__device__ float g_Ky2[(size_t)BSs * Mm * 2 * Dd];
__device__ float g_Vx[(size_t)Bb * Mm * Dd];        // V, tf32-rna, raw layout
__device__ float g_Vy[(size_t)BSs * Mm * Dd];
__device__ float g_Px[(size_t)Bb * Mm * Mm];        // probs, tf32-rna, k-permuted
__device__ float g_Py[(size_t)BSs * Mm * Mm];
__device__ unsigned char g_mx[Bb * Mm];
__device__ unsigned char g_my[BSs * Mm];

// ---------------- helpers ----------------------------------------------------
// involution permutation within 16-element groups: swaps (k%4) and ((k%16)/4)
__device__ __forceinline__ int sp(int k) {
    return (k & ~15) | ((k & 3) << 2) | ((k >> 2) & 3);
}
__device__ __forceinline__ float f_hi(float a) {
    return __uint_as_float(__float_as_uint(a) & 0xFFFFE000u);
}
__device__ __forceinline__ float tf32_rna(float a) {
    uint32_t o;
    asm("cvt.rna.tf32.f32 %0, %1;" : "=r"(o) : "f"(a));
    return __uint_as_float(o);
}
__device__ __forceinline__ uint32_t smem_u32(const void* p) {
    uint32_t a;
    asm("{ .reg .u64 t; cvta.to.shared.u64 t, %1; cvt.u32.u64 %0, t; }"
        : "=r"(a) : "l"(p));
    return a;
}
__device__ __forceinline__ void cpa16(uint32_t dst, const float* src) {
    asm volatile("cp.async.cg.shared.global [%0], [%1], 16;"
                 :: "r"(dst), "l"(src) : "memory");
}
__device__ __forceinline__ void mma_tf32(float* c, const uint32_t* a, const uint32_t* b) {
    asm volatile(
        "mma.sync.aligned.m16n8k8.row.col.f32.tf32.tf32.f32 "
        "{%0,%1,%2,%3}, {%4,%5,%6,%7}, {%8,%9}, {%0,%1,%2,%3};"
        : "+f"(c[0]), "+f"(c[1]), "+f"(c[2]), "+f"(c[3])
        : "r"(a[0]), "r"(a[1]), "r"(a[2]), "r"(a[3]), "r"(b[0]), "r"(b[1]));
}

// ---------------- cp.async stage issue ----------------------------------------
// NT smem layout: row-major, 16 floats (64B) per row, slot s (16B) at position
// s = g ^ (row & 3) holds global 16B group g. Conflict-free for stores + LDS.128.
template<bool NN_B>
__device__ __forceinline__ void issue_stage(
    const float* __restrict__ A, int lda,
    const float* __restrict__ B, int ldb, int K, int kdiv,
    int c, int nch, uint32_t asb, uint32_t bsb)
{
    if (c < nch) {
        int pass = c / kdiv;
        int kc = c - pass * kdiv;
        int acol = kc * BK + ((pass == 1) ? K : 0);
        int bcol = kc * BK + ((pass == 2) ? K : 0);
        int buf = c & (DEPTH - 1);
        uint32_t ad = asb + buf * (ASTG * 4);
        uint32_t bd = bsb + buf * ((NN_B ? BSTG_NN : BSTG_NT) * 4);
#pragma unroll
        for (int j = 0; j < 4; j++) {             // A: 256 rows x 4 slots
            int idx = threadIdx.x + 256 * j;
            int row = idx >> 2, slot = idx & 3;
            int g = slot ^ (row & 3);
            cpa16(ad + row * 64 + slot * 16,
                  A + (size_t)row * lda + acol + g * 4);
        }
        if (!NN_B) {
#pragma unroll
            for (int j = 0; j < 2; j++) {         // B NT: 128 rows x 4 slots
                int idx = threadIdx.x + 256 * j;
                int row = idx >> 2, slot = idx & 3;
                int g = slot ^ (row & 3);
                cpa16(bd + row * 64 + slot * 16,
                      B + (size_t)row * ldb + bcol + g * 4);
            }
        } else {
#pragma unroll
            for (int j = 0; j < 2; j++) {         // B NN: 16 k-rows x 32 segs
                int idx = threadIdx.x + 256 * j;
                int row = idx >> 5, seg = idx & 31;
                cpa16(bd + (row * BNNP + seg * 4) * 4,
                      B + (size_t)(bcol + row) * ldb + seg * 4);
            }
        }
    }
    asm volatile("cp.async.commit_group;" ::: "memory");
}

// ---------------- per-warp compute on one BK chunk -----------------------------
// CTA tile 256x128; 8 warps 4(m) x 2(n); warp tile 64x64.
// Vectorized frag loads: one LDS.128 yields k = {kc, kc+4, kc+8, kc+12}
// (original-k space) thanks to the global sp() permutation.
template<bool NN_B>
__device__ __forceinline__ void compute_chunk(
    const float* __restrict__ As, const float* __restrict__ Bs,
    float (&acc)[4][8][4], int wm, int wn, int gr, int kc)
{
    const int slot4 = (kc ^ (gr & 3)) * 4;
    uint32_t a[2][4][4], b[2][8][2];
#pragma unroll
    for (int mt = 0; mt < 4; mt++) {
        int r0 = wm * 64 + mt * 16 + gr;
        float4 u = *(const float4*)(As + r0 * BK + slot4);
        float4 w = *(const float4*)(As + (r0 + 8) * BK + slot4);
        a[0][mt][0] = __float_as_uint(u.x); a[0][mt][1] = __float_as_uint(w.x);
        a[0][mt][2] = __float_as_uint(u.y); a[0][mt][3] = __float_as_uint(w.y);
        a[1][mt][0] = __float_as_uint(u.z); a[1][mt][1] = __float_as_uint(w.z);
        a[1][mt][2] = __float_as_uint(u.w); a[1][mt][3] = __float_as_uint(w.w);
    }
    if (!NN_B) {
#pragma unroll
        for (int nt = 0; nt < 8; nt++) {
            int n = wn * 64 + nt * 8 + gr;
            float4 u = *(const float4*)(Bs + n * BK + slot4);
            b[0][nt][0] = __float_as_uint(u.x); b[0][nt][1] = __float_as_uint(u.y);
            b[1][nt][0] = __float_as_uint(u.z); b[1][nt][1] = __float_as_uint(u.w);
        }
    } else {
#pragma unroll
        for (int k8 = 0; k8 < 2; k8++)
#pragma unroll
            for (int nt = 0; nt < 8; nt++) {
                const float* p = Bs + (k8 * 8 + kc) * BNNP + wn * 64 + nt * 8 + gr;
                b[k8][nt][0] = __float_as_uint(p[0]);
                b[k8][nt][1] = __float_as_uint(p[4 * BNNP]);
            }
    }
#pragma unroll
    for (int k8 = 0; k8 < 2; k8++)
#pragma unroll
        for (int mt = 0; mt < 4; mt++)
#pragma unroll
            for (int nt = 0; nt < 8; nt++)
                mma_tf32(acc[mt][nt], a[k8][mt], b[k8][nt]);
}

// ---------------- pipelined GEMM over K ----------------------------------------
template<bool NN_B, int NPASS>
__device__ __forceinline__ void gemm_cp(
    const float* __restrict__ A, int lda,
    const float* __restrict__ B, int ldb, int K,
    float (&acc)[4][8][4], float* As, float* Bs, int wm, int wn, int gr, int kc)
{
    const int kdiv = K / BK;
    const int nch = NPASS * kdiv;
    uint32_t asb = smem_u32(As), bsb = smem_u32(Bs);
#pragma unroll
    for (int s = 0; s < DEPTH - 1; s++)
        issue_stage<NN_B>(A, lda, B, ldb, K, kdiv, s, nch, asb, bsb);
    for (int c = 0; c < nch; c++) {
        asm volatile("cp.async.wait_group 2;" ::: "memory");
        __syncthreads();
        int buf = c & (DEPTH - 1);
        compute_chunk<NN_B>(As + buf * ASTG,
                            Bs + buf * (NN_B ? BSTG_NN : BSTG_NT),
                            acc, wm, wn, gr, kc);
        issue_stage<NN_B>(A, lda, B, ldb, K, kdiv, c + DEPTH - 1, nch, asb, bsb);
    }
}

#define GEMM_SETUP()                                        \
    extern __shared__ float smem[];                         \
    float* As = smem;                                       \
    float* Bs = smem + DEPTH * ASTG;                        \
    int wid = threadIdx.x >> 5, lane = threadIdx.x & 31;    \
    int wm = wid >> 1, wn = wid & 1;                        \
    int gr = lane >> 2, kc = lane & 3;                      \
    float acc[4][8][4];                                     \
    _Pragma("unroll") for (int i = 0; i < 4; i++)           \
    _Pragma("unroll") for (int j = 0; j < 8; j++)           \
    _Pragma("unroll") for (int q = 0; q < 4; q++) acc[i][j][q] = 0.f;

// ---------------- fused split: x/y/W -> [hi | lo_rna], k-permuted ---------------
// Wq/Wk also get permuted ROWS (so proj emits k-permuted Q/K with vector stores);
// Wv keeps raw rows (so V / ctx stay in raw d-space).
__global__ void split_all(const float* __restrict__ x, const float* __restrict__ y,
                          const float* __restrict__ Wq, const float* __restrict__ Wk,
                          const float* __restrict__ Wv)
{
    constexpr size_t NX = (size_t)Bb * Mm * Dd;
    constexpr size_t NY = (size_t)BSs * Mm * Dd;
    constexpr size_t NW = (size_t)Dd * Dd;
    size_t i = (size_t)blockIdx.x * blockDim.x + threadIdx.x;
    if (i < NX) {
        int r = (int)(i / Dd), c = (int)(i % Dd);
        float v = x[i], h = f_hi(v);
        g_x2[(size_t)r * 512 + sp(c)] = h;
        g_x2[(size_t)r * 512 + 256 + sp(c)] = tf32_rna(v - h);
    } else if (i < NX + NY) {
        size_t e = i - NX;
        int r = (int)(e / Dd), c = (int)(e % Dd);
        float v = y[e], h = f_hi(v);
        g_y2[(size_t)r * 512 + sp(c)] = h;
        g_y2[(size_t)r * 512 + 256 + sp(c)] = tf32_rna(v - h);
    } else if (i < NX + NY + 3 * NW) {
        size_t j = i - NX - NY;
        int w = (int)(j / NW);
        size_t e = j % NW;
        int r = (int)(e / Dd), c = (int)(e % Dd);
        const float* W = (w == 0) ? Wq : (w == 1) ? Wk : Wv;
        float v = W[e], h = f_hi(v);
        int rp = (w == 2) ? r : sp(r);
        g_W2[w][(size_t)rp * 512 + sp(c)] = h;
        g_W2[w][(size_t)rp * 512 + 256 + sp(c)] = tf32_rna(v - h);
    }
}

// ---------------- projections (3xTF32): z = 0..2 x{Q,K,V}, 3..5 y{Q,K,V} -------
__global__ __launch_bounds__(256, 1) void proj_kernel()
{
    int z = blockIdx.z;
    bool isY = z >= 3;
    if (isY && blockIdx.y >= 16) return;
    int mat = z % 3;
    const float* A2 = isY ? g_y2 : g_x2;
    const float* B2 = g_W2[mat];
    int row0 = blockIdx.y * 256, col0 = blockIdx.x * 128;

    GEMM_SETUP();
    gemm_cp<false, 3>(A2 + (size_t)row0 * (2 * Dd), 2 * Dd,
                      B2 + (size_t)col0 * (2 * Dd), 2 * Dd, Dd,
                      acc, As, Bs, wm, wn, gr, kc);

    if (mat < 2) {
        // columns are already in permuted k-space (Wq/Wk rows were permuted)
        float* Q2 = (mat == 0) ? (isY ? g_Qy2 : g_Qx2) : (isY ? g_Ky2 : g_Kx2);
#pragma unroll
        for (int mt = 0; mt < 4; mt++) {
            int r = row0 + wm * 64 + mt * 16 + gr;
#pragma unroll
            for (int nt = 0; nt < 8; nt++) {
                int c = col0 + wn * 64 + nt * 8 + kc * 2;
#pragma unroll
                for (int h2 = 0; h2 < 2; h2++) {
                    int rr = r + h2 * 8;
                    float v0 = acc[mt][nt][h2 * 2], v1 = acc[mt][nt][h2 * 2 + 1];
                    float h0 = f_hi(v0), h1 = f_hi(v1);
                    *(float2*)(Q2 + (size_t)rr * 512 + c) = make_float2(h0, h1);
                    *(float2*)(Q2 + (size_t)rr * 512 + 256 + c) =
                        make_float2(tf32_rna(v0 - h0), tf32_rna(v1 - h1));
                }
            }
        }
    } else {
        float* V = isY ? g_Vy : g_Vx;   // raw d-space (Wv rows unpermuted)
#pragma unroll
        for (int mt = 0; mt < 4; mt++) {
            int r = row0 + wm * 64 + mt * 16 + gr;
#pragma unroll
            for (int nt = 0; nt < 8; nt++) {
                int c = col0 + wn * 64 + nt * 8 + kc * 2;
#pragma unroll
                for (int h2 = 0; h2 < 2; h2++) {
                    int rr = r + h2 * 8;
                    *(float2*)(V + (size_t)rr * Dd + c) =
                        make_float2(tf32_rna(acc[mt][nt][h2 * 2]),
                                    tf32_rna(acc[mt][nt][h2 * 2 + 1]));
                }
            }
        }
    }
}

// ---------------- masked score GEMMs (3xTF32 on pre-split permuted Q/K) ---------
template<int MODE>
__global__ __launch_bounds__(256, 1) void scores_kernel(float* __restrict__ outbase)
{
    int zb = blockIdx.z;
    const float *A, *Bp;
    const unsigned char *mr, *mc;
    float* C = outbase + (size_t)zb * Mm * Mm;
    if (MODE == 0) {
        A = g_Qx2 + (size_t)zb * Mm * 512; Bp = g_Kx2 + (size_t)zb * Mm * 512;
        mr = g_mx + zb * Mm; mc = mr;
    } else if (MODE == 1) {
        A = g_Qy2 + (size_t)zb * Mm * 512; Bp = g_Ky2 + (size_t)zb * Mm * 512;
        mr = g_my + zb * Mm; mc = mr;
    } else {
        int n = zb >> 3, s = zb & 7, b = s * 8 + n;
        A = g_Qx2 + (size_t)b * Mm * 512; Bp = g_Ky2 + (size_t)s * Mm * 512;
        mr = g_mx + b * Mm; mc = g_my + s * Mm;
    }
    int row0 = blockIdx.y * 256, col0 = blockIdx.x * 128;

    GEMM_SETUP();
    gemm_cp<false, 3>(A + (size_t)row0 * 512, 512,
                      Bp + (size_t)col0 * 512, 512, Dd,
                      acc, As, Bs, wm, wn, gr, kc);

#pragma unroll
    for (int mt = 0; mt < 4; mt++) {
        int r = row0 + wm * 64 + mt * 16 + gr;
        bool rm0 = mr[r] != 0, rm1 = mr[r + 8] != 0;
#pragma unroll
        for (int nt = 0; nt < 8; nt++) {
            int c = col0 + wn * 64 + nt * 8 + kc * 2;
            bool c0 = mc[c] != 0, c1 = mc[c + 1] != 0;
            float2 v0, v1;
            v0.x = (rm0 && c0) ? acc[mt][nt][0] : NEG_FILL_F;
            v0.y = (rm0 && c1) ? acc[mt][nt][1] : NEG_FILL_F;
            v1.x = (rm1 && c0) ? acc[mt][nt][2] : NEG_FILL_F;
            v1.y = (rm1 && c1) ? acc[mt][nt][3] : NEG_FILL_F;
            *(float2*)(C + (size_t)r * Mm + c) = v0;
            *(float2*)(C + (size_t)(r + 8) * Mm + c) = v1;
        }
    }
}

// ---------------- context GEMMs: ctx = P @ V (NN, 1-pass tf32) ------------------
// P is stored k-permuted (by softmax); V rows stay RAW — the vectorized A-frag
// mapping yields original tokens {kc, kc+4, kc+8, kc+12}, matching the standard
// NN b-frag row indices exactly.
__global__ __launch_bounds__(256, 1) void ctx_kernel(float* __restrict__ out, int which)
{
    int b = blockIdx.z;
    const float* P = (which ? g_Py : g_Px) + (size_t)b * Mm * Mm;
    const float* V = (which ? g_Vy : g_Vx) + (size_t)b * Mm * Dd;
    int row0 = blockIdx.y * 256, col0 = blockIdx.x * 128;

    GEMM_SETUP();
    gemm_cp<true, 1>(P + (size_t)row0 * Mm, Mm, V + col0, Dd, Mm,
                     acc, As, Bs, wm, wn, gr, kc);

    float* O = out + (size_t)b * Mm * Dd;
#pragma unroll
    for (int mt = 0; mt < 4; mt++) {
        int r = row0 + wm * 64 + mt * 16 + gr;
#pragma unroll
        for (int nt = 0; nt < 8; nt++) {
            int c = col0 + wn * 64 + nt * 8 + kc * 2;
            *(float2*)(O + (size_t)r * Dd + c) =
                make_float2(acc[mt][nt][0], acc[mt][nt][1]);
            *(float2*)(O + (size_t)(r + 8) * Dd + c) =
                make_float2(acc[mt][nt][2], acc[mt][nt][3]);
        }
    }
}

// ---------------- mask normalization (dtype-agnostic) ---------------------------
__global__ void norm_masks_kernel(const unsigned int* __restrict__ mx_in,
                                  const unsigned int* __restrict__ my_in)
{
    const unsigned int* in = (blockIdx.x == 0) ? mx_in : my_in;
    unsigned char* out = (blockIdx.x == 0) ? g_mx : g_my;
    int n = (blockIdx.x == 0) ? Bb * Mm : BSs * Mm;

    __shared__ int s_flag;
    if (threadIdx.x == 0) s_flag = 0;
    __syncthreads();
    int local = 0;
    for (int i = threadIdx.x; i < n / 4; i += blockDim.x)
        if (in[i] > 1u) local = 1;
    if (local) atomicOr(&s_flag, 1);
    __syncthreads();
    bool byte_packed = (s_flag != 0);

    const unsigned char* inb = (const unsigned char*)in;
    for (int i = threadIdx.x; i < n; i += blockDim.x)
        out[i] = byte_packed ? (inb[i] != 0 ? 1 : 0) : (in[i] != 0u ? 1 : 0);
}

// ---------------- row softmax (512 wide) -----------------------------------------
// mode 0/1: write tf32-rna probs, k-PERMUTED, to g_Px/g_Py (ctx A operand).
// mode 2: raw fp32 in place (output).
__global__ __launch_bounds__(256) void softmax_kernel(
    const float* __restrict__ in, float* __restrict__ outp, int mode)
{
    float* outbase = (mode == 0) ? g_Px : (mode == 1) ? g_Py : outp;
    size_t row = blockIdx.x;
    const float* p = in + row * Mm;
    float* o = outbase + row * Mm;
    int t = threadIdx.x;

    float v0 = p[t];
    float v1 = p[t + 256];
    float m = fmaxf(v0, v1);
#pragma unroll
    for (int off = 16; off; off >>= 1)
        m = fmaxf(m, __shfl_xor_sync(0xffffffffu, m, off));
    __shared__ float smax[8], ssum[8];
    if ((t & 31) == 0) smax[t >> 5] = m;
    __syncthreads();
    float bm = smax[0];
#pragma unroll
    for (int i = 1; i < 8; i++) bm = fmaxf(bm, smax[i]);

    float e0 = __expf(v0 - bm);
    float e1 = __expf(v1 - bm);
    float s = e0 + e1;
#pragma unroll
    for (int off = 16; off; off >>= 1)
        s += __shfl_xor_sync(0xffffffffu, s, off);
    if ((t & 31) == 0) ssum[t >> 5] = s;
    __syncthreads();
    float tot = 0.f;
#pragma unroll
    for (int i = 0; i < 8; i++) tot += ssum[i];
    float inv = 1.0f / tot;
    if (mode < 2) {
        o[sp(t)] = tf32_rna(e0 * inv);
        o[sp(t + 256)] = tf32_rna(e1 * inv);
    } else {
        o[t] = e0 * inv;
        o[t + 256] = e1 * inv;
    }
}

// ---------------- mask_xy as floats, y_len ----------------------------------------
__global__ void mask_xy_kernel(float* __restrict__ out)
{
    int rowid = blockIdx.x;
    int i = rowid & 511;
    int s = (rowid >> 9) & 7;
    int n = rowid >> 12;
    bool rm = g_mx[(s * 8 + n) * Mm + i] != 0;
    float* o = out + (size_t)rowid * Mm;
    for (int j = threadIdx.x; j < Mm; j += blockDim.x)
        o[j] = rm ? (g_my[s * Mm + j] ? 1.0f : 0.0f) : 0.0f;
}

__global__ void ylen_kernel(float* __restrict__ out)
{
    int t = threadIdx.x;
    if (t >= 64) return;
    int s = t & 7;
    int sum = 0;
    for (int j = 0; j < Mm; j++) sum += g_my[s * Mm + j] ? 1 : 0;
    out[t] = (float)sum;
}

// ---------------- launch ------------------------------------------------------------
extern "C" void kernel_launch(void* const* d_in, const int* in_sizes, int n_in,
                              void* d_out, int out_size)
{
    const float* x  = (const float*)d_in[0];
    const float* y  = (const float*)d_in[1];
    const unsigned int* mask_x = (const unsigned int*)d_in[2];
    const unsigned int* mask_y = (const unsigned int*)d_in[3];
    const float* Wq = (const float*)d_in[4];
    const float* Wk = (const float*)d_in[5];
    const float* Wv = (const float*)d_in[6];

    float* out = (float*)d_out;
    float* out_ctx_x = out;                    // 64*512*256
    float* out_ctx_y = out + 8388608;          // 8*512*256
    float* out_sx    = out + 9437184;          // 64*512*512
    float* out_sy    = out + 26214400;         // 8*512*512
    float* out_pxy   = out + 28311552;         // 64*512*512
    float* out_mxy   = out + 45088768;         // 64*512*512
    float* out_ylen  = out + 61865984;         // 64

    cudaFuncSetAttribute(proj_kernel, cudaFuncAttributeMaxDynamicSharedMemorySize, DSMEM_NT);
    cudaFuncSetAttribute(scores_kernel<0>, cudaFuncAttributeMaxDynamicSharedMemorySize, DSMEM_NT);
    cudaFuncSetAttribute(scores_kernel<1>, cudaFuncAttributeMaxDynamicSharedMemorySize, DSMEM_NT);
    cudaFuncSetAttribute(scores_kernel<2>, cudaFuncAttributeMaxDynamicSharedMemorySize, DSMEM_NT);
    cudaFuncSetAttribute(ctx_kernel, cudaFuncAttributeMaxDynamicSharedMemorySize, DSMEM_NN);

    dim3 blk(256);

    // launches ordered so that launch #6 (ncu -s 5 -c 1) = scores_kernel<0>
    norm_masks_kernel<<<2, 1024>>>(mask_x, mask_y);                       // 1
    {
        constexpr size_t TOT = (size_t)Bb * Mm * Dd + (size_t)BSs * Mm * Dd
                             + 3 * (size_t)Dd * Dd;
        split_all<<<(unsigned)((TOT + 255) / 256), 256>>>(x, y, Wq, Wk, Wv);  // 2
    }
    proj_kernel<<<dim3(2, 128, 6), blk, DSMEM_NT>>>();                    // 3
    scores_kernel<1><<<dim3(4, 2, 8),  blk, DSMEM_NT>>>(out_sy);          // 4
    scores_kernel<2><<<dim3(4, 2, 64), blk, DSMEM_NT>>>(out_pxy);         // 5
    scores_kernel<0><<<dim3(4, 2, 64), blk, DSMEM_NT>>>(out_sx);          // 6 <- profiled

    softmax_kernel<<<Bb * Mm, 256>>>(out_sx, nullptr, 0);
    softmax_kernel<<<BSs * Mm, 256>>>(out_sy, nullptr, 1);
    softmax_kernel<<<Bb * Mm, 256>>>(out_pxy, out_pxy, 2);

    ctx_kernel<<<dim3(2, 2, 64), blk, DSMEM_NN>>>(out_ctx_x, 0);
    ctx_kernel<<<dim3(2, 2, 8),  blk, DSMEM_NN>>>(out_ctx_y, 1);

    mask_xy_kernel<<<Bb * Mm, 128>>>(out_mxy);
    ylen_kernel<<<1, 64>>>(out_ylen);
}

// round 7
// speedup vs baseline: 1.3315x; 1.0505x over previous
#include <cuda_runtime.h>
#include <cstdint>

constexpr int Bb  = 64;
constexpr int BSs = 8;
constexpr int Mm  = 512;
constexpr int Dd  = 256;
constexpr float NEG_FILL_F = -10000000000.0f;

constexpr int BK    = 16;
constexpr int BNNP  = 136;              // NN B row stride (ctx V path)
constexpr int DEPTH = 4;
constexpr int ASTG    = 128 * BK;       // 2048 floats per A stage (8KB)
constexpr int BSTG_NT = 128 * BK;       // 2048 floats
constexpr int BSTG_NN = BK * BNNP;      // 2176 floats
constexpr int DSMEM_NT = DEPTH * (ASTG + BSTG_NT) * 4;   // 65536 B
constexpr int DSMEM_NN = DEPTH * (ASTG + BSTG_NN) * 4;   // 67584 B

// ---------------- scratch (static device memory) ----------------------------
__device__ float g_x2[(size_t)Bb * Mm * 2 * Dd];    // x split [hi|lo], k-permuted
__device__ float g_y2[(size_t)BSs * Mm * 2 * Dd];
__device__ float g_W2[3][(size_t)Dd * 2 * Dd];      // W split; q/k rows permuted too
__device__ float g_Qx2[(size_t)Bb * Mm * 2 * Dd];   // Q split, k-permuted
__device__ float g_Kx2[(size_t)Bb * Mm * 2 * Dd];
__device__ float g_Qy2[(size_t)BSs * Mm * 2 * Dd];
__device__ float g_Ky2[(size_t)BSs * Mm * 2 * Dd];
__device__ float g_Vx[(size_t)Bb * Mm * Dd];        // V, tf32-rna, raw layout
__device__ float g_Vy[(size_t)BSs * Mm * Dd];
__device__ float g_Px[(size_t)Bb * Mm * Mm];        // probs, tf32-rna, k-permuted
__device__ float g_Py[(size_t)BSs * Mm * Mm];
__device__ unsigned char g_mx[Bb * Mm];
__device__ unsigned char g_my[BSs * Mm];

// ---------------- helpers ----------------------------------------------------
// involution permutation within 16-element groups: swaps (k%4) and ((k%16)/4)
__device__ __forceinline__ int sp(int k) {
    return (k & ~15) | ((k & 3) << 2) | ((k >> 2) & 3);
}
__device__ __forceinline__ float f_hi(float a) {
    return __uint_as_float(__float_as_uint(a) & 0xFFFFE000u);
}
__device__ __forceinline__ float tf32_rna(float a) {
    uint32_t o;
    asm("cvt.rna.tf32.f32 %0, %1;" : "=r"(o) : "f"(a));
    return __uint_as_float(o);
}
__device__ __forceinline__ uint32_t smem_u32(const void* p) {
    uint32_t a;
    asm("{ .reg .u64 t; cvta.to.shared.u64 t, %1; cvt.u32.u64 %0, t; }"
        : "=r"(a) : "l"(p));
    return a;
}
__device__ __forceinline__ void cpa16(uint32_t dst, const float* src) {
    asm volatile("cp.async.cg.shared.global [%0], [%1], 16;"
                 :: "r"(dst), "l"(src) : "memory");
}
__device__ __forceinline__ void mma_tf32(float* c, const uint32_t* a, const uint32_t* b) {
    asm volatile(
        "mma.sync.aligned.m16n8k8.row.col.f32.tf32.tf32.f32 "
        "{%0,%1,%2,%3}, {%4,%5,%6,%7}, {%8,%9}, {%0,%1,%2,%3};"
        : "+f"(c[0]), "+f"(c[1]), "+f"(c[2]), "+f"(c[3])
        : "r"(a[0]), "r"(a[1]), "r"(a[2]), "r"(a[3]), "r"(b[0]), "r"(b[1]));
}

// ---------------- cp.async stage issue ----------------------------------------
// NT smem layout: row-major, 16 floats (64B) per row, slot s (16B) at position
// s = g ^ (row & 3) holds global 16B group g. Conflict-free stores + LDS.128.
template<bool NN_B>
__device__ __forceinline__ void issue_stage(
    const float* __restrict__ A, int lda,
    const float* __restrict__ B, int ldb, int K, int kdiv,
    int c, int nch, uint32_t asb, uint32_t bsb)
{
    if (c < nch) {
        int pass = c / kdiv;
        int kc = c - pass * kdiv;
        int acol = kc * BK + ((pass == 1) ? K : 0);
        int bcol = kc * BK + ((pass == 2) ? K : 0);
        int buf = c & (DEPTH - 1);
        uint32_t ad = asb + buf * (ASTG * 4);
        uint32_t bd = bsb + buf * ((NN_B ? BSTG_NN : BSTG_NT) * 4);
#pragma unroll
        for (int j = 0; j < 2; j++) {             // A: 128 rows x 4 slots
            int idx = threadIdx.x + 256 * j;
            int row = idx >> 2, slot = idx & 3;
            int g = slot ^ (row & 3);
            cpa16(ad + row * 64 + slot * 16,
                  A + (size_t)row * lda + acol + g * 4);
        }
        if (!NN_B) {
#pragma unroll
            for (int j = 0; j < 2; j++) {         // B NT: 128 rows x 4 slots
                int idx = threadIdx.x + 256 * j;
                int row = idx >> 2, slot = idx & 3;
                int g = slot ^ (row & 3);
                cpa16(bd + row * 64 + slot * 16,
                      B + (size_t)row * ldb + bcol + g * 4);
            }
        } else {
#pragma unroll
            for (int j = 0; j < 2; j++) {         // B NN: 16 k-rows x 32 segs
                int idx = threadIdx.x + 256 * j;
                int row = idx >> 5, seg = idx & 31;
                cpa16(bd + (row * BNNP + seg * 4) * 4,
                      B + (size_t)(bcol + row) * ldb + seg * 4);
            }
        }
    }
    asm volatile("cp.async.commit_group;" ::: "memory");
}

// ---------------- per-warp compute on one BK chunk -----------------------------
// CTA tile 128x128; 8 warps 2(m) x 4(n); warp tile 64x32.
// Vectorized frag loads: one LDS.128 yields k = {kc, kc+4, kc+8, kc+12}
// (original-k space) thanks to the global sp() permutation.
template<bool NN_B>
__device__ __forceinline__ void compute_chunk(
    const float* __restrict__ As, const float* __restrict__ Bs,
    float (&acc)[4][4][4], int wm, int wn, int gr, int kc)
{
    const int slot4 = (kc ^ (gr & 3)) * 4;
    uint32_t a[2][4][4], b[2][4][2];
#pragma unroll
    for (int mt = 0; mt < 4; mt++) {
        int r0 = wm * 64 + mt * 16 + gr;
        float4 u = *(const float4*)(As + r0 * BK + slot4);
        float4 w = *(const float4*)(As + (r0 + 8) * BK + slot4);
        a[0][mt][0] = __float_as_uint(u.x); a[0][mt][1] = __float_as_uint(w.x);
        a[0][mt][2] = __float_as_uint(u.y); a[0][mt][3] = __float_as_uint(w.y);
        a[1][mt][0] = __float_as_uint(u.z); a[1][mt][1] = __float_as_uint(w.z);
        a[1][mt][2] = __float_as_uint(u.w); a[1][mt][3] = __float_as_uint(w.w);
    }
    if (!NN_B) {
#pragma unroll
        for (int nt = 0; nt < 4; nt++) {
            int n = wn * 32 + nt * 8 + gr;
            float4 u = *(const float4*)(Bs + n * BK + slot4);
            b[0][nt][0] = __float_as_uint(u.x); b[0][nt][1] = __float_as_uint(u.y);
            b[1][nt][0] = __float_as_uint(u.z); b[1][nt][1] = __float_as_uint(u.w);
        }
    } else {
#pragma unroll
        for (int k8 = 0; k8 < 2; k8++)
#pragma unroll
            for (int nt = 0; nt < 4; nt++) {
                const float* p = Bs + (k8 * 8 + kc) * BNNP + wn * 32 + nt * 8 + gr;
                b[k8][nt][0] = __float_as_uint(p[0]);
                b[k8][nt][1] = __float_as_uint(p[4 * BNNP]);
            }
    }
#pragma unroll
    for (int k8 = 0; k8 < 2; k8++)
#pragma unroll
        for (int mt = 0; mt < 4; mt++)
#pragma unroll
            for (int nt = 0; nt < 4; nt++)
                mma_tf32(acc[mt][nt], a[k8][mt], b[k8][nt]);
}

// ---------------- pipelined GEMM over K ----------------------------------------
template<bool NN_B, int NPASS>
__device__ __forceinline__ void gemm_cp(
    const float* __restrict__ A, int lda,
    const float* __restrict__ B, int ldb, int K,
    float (&acc)[4][4][4], float* As, float* Bs, int wm, int wn, int gr, int kc)
{
    const int kdiv = K / BK;
    const int nch = NPASS * kdiv;
    uint32_t asb = smem_u32(As), bsb = smem_u32(Bs);
#pragma unroll
    for (int s = 0; s < DEPTH - 1; s++)
        issue_stage<NN_B>(A, lda, B, ldb, K, kdiv, s, nch, asb, bsb);
    for (int c = 0; c < nch; c++) {
        asm volatile("cp.async.wait_group 2;" ::: "memory");
        __syncthreads();
        issue_stage<NN_B>(A, lda, B, ldb, K, kdiv, c + DEPTH - 1, nch, asb, bsb);
        int buf = c & (DEPTH - 1);
        compute_chunk<NN_B>(As + buf * ASTG,
                            Bs + buf * (NN_B ? BSTG_NN : BSTG_NT),
                            acc, wm, wn, gr, kc);
    }
}

#define GEMM_SETUP()                                        \
    extern __shared__ float smem[];                         \
    float* As = smem;                                       \
    float* Bs = smem + DEPTH * ASTG;                        \
    int wid = threadIdx.x >> 5, lane = threadIdx.x & 31;    \
    int wm = wid >> 2, wn = wid & 3;                        \
    int gr = lane >> 2, kc = lane & 3;                      \
    float acc[4][4][4];                                     \
    _Pragma("unroll") for (int i = 0; i < 4; i++)           \
    _Pragma("unroll") for (int j = 0; j < 4; j++)           \
    _Pragma("unroll") for (int q = 0; q < 4; q++) acc[i][j][q] = 0.f;

// ---------------- fused split: x/y/W -> [hi | lo_rna], k-permuted ---------------
// Wq/Wk also get permuted ROWS (so proj emits k-permuted Q/K with vector stores);
// Wv keeps raw rows (so V / ctx stay in raw d-space).
__global__ void split_all(const float* __restrict__ x, const float* __restrict__ y,
                          const float* __restrict__ Wq, const float* __restrict__ Wk,
                          const float* __restrict__ Wv)
{
    constexpr size_t NX = (size_t)Bb * Mm * Dd;
    constexpr size_t NY = (size_t)BSs * Mm * Dd;
    constexpr size_t NW = (size_t)Dd * Dd;
    size_t i = (size_t)blockIdx.x * blockDim.x + threadIdx.x;
    if (i < NX) {
        int r = (int)(i / Dd), c = (int)(i % Dd);
        float v = x[i], h = f_hi(v);
        g_x2[(size_t)r * 512 + sp(c)] = h;
        g_x2[(size_t)r * 512 + 256 + sp(c)] = tf32_rna(v - h);
    } else if (i < NX + NY) {
        size_t e = i - NX;
        int r = (int)(e / Dd), c = (int)(e % Dd);
        float v = y[e], h = f_hi(v);
        g_y2[(size_t)r * 512 + sp(c)] = h;
        g_y2[(size_t)r * 512 + 256 + sp(c)] = tf32_rna(v - h);
    } else if (i < NX + NY + 3 * NW) {
        size_t j = i - NX - NY;
        int w = (int)(j / NW);
        size_t e = j % NW;
        int r = (int)(e / Dd), c = (int)(e % Dd);
        const float* W = (w == 0) ? Wq : (w == 1) ? Wk : Wv;
        float v = W[e], h = f_hi(v);
        int rp = (w == 2) ? r : sp(r);
        g_W2[w][(size_t)rp * 512 + sp(c)] = h;
        g_W2[w][(size_t)rp * 512 + 256 + sp(c)] = tf32_rna(v - h);
    }
}

// ---------------- projections (3xTF32): z = 0..2 x{Q,K,V}, 3..5 y{Q,K,V} -------
__global__ __launch_bounds__(256, 2) void proj_kernel()
{
    int z = blockIdx.z;
    bool isY = z >= 3;
    if (isY && blockIdx.y >= 32) return;
    int mat = z % 3;
    const float* A2 = isY ? g_y2 : g_x2;
    const float* B2 = g_W2[mat];
    int row0 = blockIdx.y * 128, col0 = blockIdx.x * 128;

    GEMM_SETUP();
    gemm_cp<false, 3>(A2 + (size_t)row0 * (2 * Dd), 2 * Dd,
                      B2 + (size_t)col0 * (2 * Dd), 2 * Dd, Dd,
                      acc, As, Bs, wm, wn, gr, kc);

    if (mat < 2) {
        // columns already in permuted k-space (Wq/Wk rows were permuted)
        float* Q2 = (mat == 0) ? (isY ? g_Qy2 : g_Qx2) : (isY ? g_Ky2 : g_Kx2);
#pragma unroll
        for (int mt = 0; mt < 4; mt++) {
            int r = row0 + wm * 64 + mt * 16 + gr;
#pragma unroll
            for (int nt = 0; nt < 4; nt++) {
                int c = col0 + wn * 32 + nt * 8 + kc * 2;
#pragma unroll
                for (int h2 = 0; h2 < 2; h2++) {
                    int rr = r + h2 * 8;
                    float v0 = acc[mt][nt][h2 * 2], v1 = acc[mt][nt][h2 * 2 + 1];
                    float h0 = f_hi(v0), h1 = f_hi(v1);
                    *(float2*)(Q2 + (size_t)rr * 512 + c) = make_float2(h0, h1);
                    *(float2*)(Q2 + (size_t)rr * 512 + 256 + c) =
                        make_float2(tf32_rna(v0 - h0), tf32_rna(v1 - h1));
                }
            }
        }
    } else {
        float* V = isY ? g_Vy : g_Vx;   // raw d-space (Wv rows unpermuted)
#pragma unroll
        for (int mt = 0; mt < 4; mt++) {
            int r = row0 + wm * 64 + mt * 16 + gr;
#pragma unroll
            for (int nt = 0; nt < 4; nt++) {
                int c = col0 + wn * 32 + nt * 8 + kc * 2;
#pragma unroll
                for (int h2 = 0; h2 < 2; h2++) {
                    int rr = r + h2 * 8;
                    *(float2*)(V + (size_t)rr * Dd + c) =
                        make_float2(tf32_rna(acc[mt][nt][h2 * 2]),
                                    tf32_rna(acc[mt][nt][h2 * 2 + 1]));
                }
            }
        }
    }
}

// ---------------- masked score GEMMs (3xTF32 on pre-split permuted Q/K) ---------
template<int MODE>
__global__ __launch_bounds__(256, 2) void scores_kernel(float* __restrict__ outbase)
{
    int zb = blockIdx.z;
    const float *A, *Bp;
    const unsigned char *mr, *mc;
    float* C = outbase + (size_t)zb * Mm * Mm;
    if (MODE == 0) {
        A = g_Qx2 + (size_t)zb * Mm * 512; Bp = g_Kx2 + (size_t)zb * Mm * 512;
        mr = g_mx + zb * Mm; mc = mr;
    } else if (MODE == 1) {
        A = g_Qy2 + (size_t)zb * Mm * 512; Bp = g_Ky2 + (size_t)zb * Mm * 512;
        mr = g_my + zb * Mm; mc = mr;
    } else {
        int n = zb >> 3, s = zb & 7, b = s * 8 + n;
        A = g_Qx2 + (size_t)b * Mm * 512; Bp = g_Ky2 + (size_t)s * Mm * 512;
        mr = g_mx + b * Mm; mc = g_my + s * Mm;
    }
    int row0 = blockIdx.y * 128, col0 = blockIdx.x * 128;

    GEMM_SETUP();
    gemm_cp<false, 3>(A + (size_t)row0 * 512, 512,
                      Bp + (size_t)col0 * 512, 512, Dd,
                      acc, As, Bs, wm, wn, gr, kc);

#pragma unroll
    for (int mt = 0; mt < 4; mt++) {
        int r = row0 + wm * 64 + mt * 16 + gr;
        bool rm0 = mr[r] != 0, rm1 = mr[r + 8] != 0;
#pragma unroll
        for (int nt = 0; nt < 4; nt++) {
            int c = col0 + wn * 32 + nt * 8 + kc * 2;
            bool c0 = mc[c] != 0, c1 = mc[c + 1] != 0;
            float2 v0, v1;
            v0.x = (rm0 && c0) ? acc[mt][nt][0] : NEG_FILL_F;
            v0.y = (rm0 && c1) ? acc[mt][nt][1] : NEG_FILL_F;
            v1.x = (rm1 && c0) ? acc[mt][nt][2] : NEG_FILL_F;
            v1.y = (rm1 && c1) ? acc[mt][nt][3] : NEG_FILL_F;
            *(float2*)(C + (size_t)r * Mm + c) = v0;
            *(float2*)(C + (size_t)(r + 8) * Mm + c) = v1;
        }
    }
}

// ---------------- context GEMMs: ctx = P @ V (NN, 1-pass tf32) ------------------
// P stored k-permuted (by softmax); V rows RAW — vectorized A-frag mapping
// yields original tokens {kc, kc+4, kc+8, kc+12}, matching NN b-frag rows.
__global__ __launch_bounds__(256, 2) void ctx_kernel(float* __restrict__ out, int which)
{
    int b = blockIdx.z;
    const float* P = (which ? g_Py : g_Px) + (size_t)b * Mm * Mm;
    const float* V = (which ? g_Vy : g_Vx) + (size_t)b * Mm * Dd;
    int row0 = blockIdx.y * 128, col0 = blockIdx.x * 128;

    GEMM_SETUP();
    gemm_cp<true, 1>(P + (size_t)row0 * Mm, Mm, V + col0, Dd, Mm,
                     acc, As, Bs, wm, wn, gr, kc);

    float* O = out + (size_t)b * Mm * Dd;
#pragma unroll
    for (int mt = 0; mt < 4; mt++) {
        int r = row0 + wm * 64 + mt * 16 + gr;
#pragma unroll
        for (int nt = 0; nt < 4; nt++) {
            int c = col0 + wn * 32 + nt * 8 + kc * 2;
            *(float2*)(O + (size_t)r * Dd + c) =
                make_float2(acc[mt][nt][0], acc[mt][nt][1]);
            *(float2*)(O + (size_t)(r + 8) * Dd + c) =
                make_float2(acc[mt][nt][2], acc[mt][nt][3]);
        }
    }
}

// ---------------- mask normalization (dtype-agnostic) ---------------------------
__global__ void norm_masks_kernel(const unsigned int* __restrict__ mx_in,
                                  const unsigned int* __restrict__ my_in)
{
    const unsigned int* in = (blockIdx.x == 0) ? mx_in : my_in;
    unsigned char* out = (blockIdx.x == 0) ? g_mx : g_my;
    int n = (blockIdx.x == 0) ? Bb * Mm : BSs * Mm;

    __shared__ int s_flag;
    if (threadIdx.x == 0) s_flag = 0;
    __syncthreads();
    int local = 0;
    for (int i = threadIdx.x; i < n / 4; i += blockDim.x)
        if (in[i] > 1u) local = 1;
    if (local) atomicOr(&s_flag, 1);
    __syncthreads();
    bool byte_packed = (s_flag != 0);

    const unsigned char* inb = (const unsigned char*)in;
    for (int i = threadIdx.x; i < n; i += blockDim.x)
        out[i] = byte_packed ? (inb[i] != 0 ? 1 : 0) : (in[i] != 0u ? 1 : 0);
}

// ---------------- row softmax (512 wide) -----------------------------------------
// mode 0/1: write tf32-rna probs, k-PERMUTED, to g_Px/g_Py (ctx A operand).
// mode 2: raw fp32 in place (output).
__global__ __launch_bounds__(256) void softmax_kernel(
    const float* __restrict__ in, float* __restrict__ outp, int mode)
{
    float* outbase = (mode == 0) ? g_Px : (mode == 1) ? g_Py : outp;
    size_t row = blockIdx.x;
    const float* p = in + row * Mm;
    float* o = outbase + row * Mm;
    int t = threadIdx.x;

    float v0 = p[t];
    float v1 = p[t + 256];
    float m = fmaxf(v0, v1);
#pragma unroll
    for (int off = 16; off; off >>= 1)
        m = fmaxf(m, __shfl_xor_sync(0xffffffffu, m, off));
    __shared__ float smax[8], ssum[8];
    if ((t & 31) == 0) smax[t >> 5] = m;
    __syncthreads();
    float bm = smax[0];
#pragma unroll
    for (int i = 1; i < 8; i++) bm = fmaxf(bm, smax[i]);

    float e0 = __expf(v0 - bm);
    float e1 = __expf(v1 - bm);
    float s = e0 + e1;
#pragma unroll
    for (int off = 16; off; off >>= 1)
        s += __shfl_xor_sync(0xffffffffu, s, off);
    if ((t & 31) == 0) ssum[t >> 5] = s;
    __syncthreads();
    float tot = 0.f;
#pragma unroll
    for (int i = 0; i < 8; i++) tot += ssum[i];
    float inv = 1.0f / tot;
    if (mode < 2) {
        o[sp(t)] = tf32_rna(e0 * inv);
        o[sp(t + 256)] = tf32_rna(e1 * inv);
    } else {
        o[t] = e0 * inv;
        o[t + 256] = e1 * inv;
    }
}

// ---------------- mask_xy as floats, y_len ----------------------------------------
__global__ void mask_xy_kernel(float* __restrict__ out)
{
    int rowid = blockIdx.x;
    int i = rowid & 511;
    int s = (rowid >> 9) & 7;
    int n = rowid >> 12;
    bool rm = g_mx[(s * 8 + n) * Mm + i] != 0;
    float* o = out + (size_t)rowid * Mm;
    for (int j = threadIdx.x; j < Mm; j += blockDim.x)
        o[j] = rm ? (g_my[s * Mm + j] ? 1.0f : 0.0f) : 0.0f;
}

__global__ void ylen_kernel(float* __restrict__ out)
{
    int t = threadIdx.x;
    if (t >= 64) return;
    int s = t & 7;
    int sum = 0;
    for (int j = 0; j < Mm; j++) sum += g_my[s * Mm + j] ? 1 : 0;
    out[t] = (float)sum;
}

// ---------------- launch ------------------------------------------------------------
extern "C" void kernel_launch(void* const* d_in, const int* in_sizes, int n_in,
                              void* d_out, int out_size)
{
    const float* x  = (const float*)d_in[0];
    const float* y  = (const float*)d_in[1];
    const unsigned int* mask_x = (const unsigned int*)d_in[2];
    const unsigned int* mask_y = (const unsigned int*)d_in[3];
    const float* Wq = (const float*)d_in[4];
    const float* Wk = (const float*)d_in[5];
    const float* Wv = (const float*)d_in[6];

    float* out = (float*)d_out;
    float* out_ctx_x = out;                    // 64*512*256
    float* out_ctx_y = out + 8388608;          // 8*512*256
    float* out_sx    = out + 9437184;          // 64*512*512
    float* out_sy    = out + 26214400;         // 8*512*512
    float* out_pxy   = out + 28311552;         // 64*512*512
    float* out_mxy   = out + 45088768;         // 64*512*512
    float* out_ylen  = out + 61865984;         // 64

    cudaFuncSetAttribute(proj_kernel, cudaFuncAttributeMaxDynamicSharedMemorySize, DSMEM_NT);
    cudaFuncSetAttribute(scores_kernel<0>, cudaFuncAttributeMaxDynamicSharedMemorySize, DSMEM_NT);
    cudaFuncSetAttribute(scores_kernel<1>, cudaFuncAttributeMaxDynamicSharedMemorySize, DSMEM_NT);
    cudaFuncSetAttribute(scores_kernel<2>, cudaFuncAttributeMaxDynamicSharedMemorySize, DSMEM_NT);
    cudaFuncSetAttribute(ctx_kernel, cudaFuncAttributeMaxDynamicSharedMemorySize, DSMEM_NN);

    dim3 blk(256);

    norm_masks_kernel<<<2, 1024>>>(mask_x, mask_y);                       // 1
    {
        constexpr size_t TOT = (size_t)Bb * Mm * Dd + (size_t)BSs * Mm * Dd
                             + 3 * (size_t)Dd * Dd;
        split_all<<<(unsigned)((TOT + 255) / 256), 256>>>(x, y, Wq, Wk, Wv);  // 2
    }
    proj_kernel<<<dim3(2, 256, 6), blk, DSMEM_NT>>>();                    // 3
    scores_kernel<1><<<dim3(4, 4, 8),  blk, DSMEM_NT>>>(out_sy);          // 4
    scores_kernel<2><<<dim3(4, 4, 64), blk, DSMEM_NT>>>(out_pxy);         // 5
    scores_kernel<0><<<dim3(4, 4, 64), blk, DSMEM_NT>>>(out_sx);          // 6

    softmax_kernel<<<Bb * Mm, 256>>>(out_sx, nullptr, 0);
    softmax_kernel<<<BSs * Mm, 256>>>(out_sy, nullptr, 1);
    softmax_kernel<<<Bb * Mm, 256>>>(out_pxy, out_pxy, 2);

    ctx_kernel<<<dim3(2, 4, 64), blk, DSMEM_NN>>>(out_ctx_x, 0);
    ctx_kernel<<<dim3(2, 4, 8),  blk, DSMEM_NN>>>(out_ctx_y, 1);

    mask_xy_kernel<<<Bb * Mm, 128>>>(out_mxy);
    ylen_kernel<<<1, 64>>>(out_ylen);
}

// round 8
// speedup vs baseline: 2.1440x; 1.6103x over previous
#include <cuda_runtime.h>
#include <cuda_bf16.h>
#include <cstdint>

constexpr int Bb  = 64;
constexpr int BSs = 8;
constexpr int Mm  = 512;
constexpr int Dd  = 256;
constexpr float NEG_FILL_F = -10000000000.0f;

constexpr int DEPTH = 4;
// bf16 NT path: chunk = 32 bf16 k (64B/row), tiles 128 rows -> 8KB per stage side
constexpr int BSTAGE = 8192;                       // bytes per tile stage
constexpr int DSMEM_BF = DEPTH * 2 * BSTAGE;       // 65536 B
// fp32 NN path (ctx): BK=16 fp32
constexpr int BK32   = 16;
constexpr int BNNP   = 136;
constexpr int ASTG32   = 128 * BK32;               // floats
constexpr int BSTG_NN  = BK32 * BNNP;              // floats
constexpr int DSMEM_NN = DEPTH * (ASTG32 + BSTG_NN) * 4;  // 67584 B

// ---------------- scratch ------------------------------------------------------
__device__ __nv_bfloat16 g_x2[(size_t)Bb * Mm * 2 * Dd];   // [hi|lo] width 512
__device__ __nv_bfloat16 g_y2[(size_t)BSs * Mm * 2 * Dd];
__device__ __nv_bfloat16 g_W2[3][(size_t)Dd * 2 * Dd];
__device__ __nv_bfloat16 g_Qx2[(size_t)Bb * Mm * 2 * Dd];
__device__ __nv_bfloat16 g_Kx2[(size_t)Bb * Mm * 2 * Dd];
__device__ __nv_bfloat16 g_Qy2[(size_t)BSs * Mm * 2 * Dd];
__device__ __nv_bfloat16 g_Ky2[(size_t)BSs * Mm * 2 * Dd];
__device__ float g_Vx[(size_t)Bb * Mm * Dd];        // V fp32 tf32-rna
__device__ float g_Vy[(size_t)BSs * Mm * Dd];
__device__ float g_Px[(size_t)Bb * Mm * Mm];        // probs tf32-rna, sp-permuted
__device__ float g_Py[(size_t)BSs * Mm * Mm];
__device__ unsigned char g_mx[Bb * Mm];
__device__ unsigned char g_my[BSs * Mm];

// ---------------- helpers ------------------------------------------------------
__device__ __forceinline__ int sp(int k) {          // involution, used for P only
    return (k & ~15) | ((k & 3) << 2) | ((k >> 2) & 3);
}
__device__ __forceinline__ float tf32_rna(float a) {
    uint32_t o;
    asm("cvt.rna.tf32.f32 %0, %1;" : "=r"(o) : "f"(a));
    return __uint_as_float(o);
}
__device__ __forceinline__ uint32_t smem_u32(const void* p) {
    uint32_t a;
    asm("{ .reg .u64 t; cvta.to.shared.u64 t, %1; cvt.u32.u64 %0, t; }"
        : "=r"(a) : "l"(p));
    return a;
}
__device__ __forceinline__ void cpa16(uint32_t dst, const void* src) {
    asm volatile("cp.async.cg.shared.global [%0], [%1], 16;"
                 :: "r"(dst), "l"(src) : "memory");
}
__device__ __forceinline__ void ldm_x4(uint32_t* r, uint32_t addr) {
    asm volatile("ldmatrix.sync.aligned.m8n8.x4.shared.b16 {%0,%1,%2,%3}, [%4];"
        : "=r"(r[0]), "=r"(r[1]), "=r"(r[2]), "=r"(r[3]) : "r"(addr));
}
__device__ __forceinline__ void mma_bf16(float* c, const uint32_t* a,
                                         uint32_t b0, uint32_t b1) {
    asm volatile(
        "mma.sync.aligned.m16n8k16.row.col.f32.bf16.bf16.f32 "
        "{%0,%1,%2,%3}, {%4,%5,%6,%7}, {%8,%9}, {%0,%1,%2,%3};"
        : "+f"(c[0]), "+f"(c[1]), "+f"(c[2]), "+f"(c[3])
        : "r"(a[0]), "r"(a[1]), "r"(a[2]), "r"(a[3]), "r"(b0), "r"(b1));
}
__device__ __forceinline__ void mma_tf32(float* c, const uint32_t* a, const uint32_t* b) {
    asm volatile(
        "mma.sync.aligned.m16n8k8.row.col.f32.tf32.tf32.f32 "
        "{%0,%1,%2,%3}, {%4,%5,%6,%7}, {%8,%9}, {%0,%1,%2,%3};"
        : "+f"(c[0]), "+f"(c[1]), "+f"(c[2]), "+f"(c[3])
        : "r"(a[0]), "r"(a[1]), "r"(a[2]), "r"(a[3]), "r"(b[0]), "r"(b[1]));
}

// ============================ bf16 NT GEMM path ================================
// smem tile: 128 rows x 64B (32 bf16). Slot swizzle: phys_slot = g ^ ((row>>1)&3).
// 3 passes (hi,hi),(lo,hi),(hi,lo) over [hi|lo]-concat bf16 operands (width 512).
__device__ __forceinline__ void issue_stage_bf16(
    const __nv_bfloat16* __restrict__ A, const __nv_bfloat16* __restrict__ B,
    int c, int nch, uint32_t asb, uint32_t bsb)
{
    constexpr int kdiv = 8;
    if (c < nch) {
        int pass = c / kdiv;
        int kc = c - pass * kdiv;
        int aoff = kc * 32 + ((pass == 1) ? 256 : 0);
        int boff = kc * 32 + ((pass == 2) ? 256 : 0);
        int buf = c & (DEPTH - 1);
        uint32_t ad = asb + buf * BSTAGE;
        uint32_t bd = bsb + buf * BSTAGE;
#pragma unroll
        for (int j = 0; j < 2; j++) {
            int idx = threadIdx.x + 256 * j;
            int row = idx >> 2, slot = idx & 3;
            int g = slot ^ ((row >> 1) & 3);
            cpa16(ad + row * 64 + slot * 16, A + (size_t)row * 512 + aoff + g * 8);
        }
#pragma unroll
        for (int j = 0; j < 2; j++) {
            int idx = threadIdx.x + 256 * j;
            int row = idx >> 2, slot = idx & 3;
            int g = slot ^ ((row >> 1) & 3);
            cpa16(bd + row * 64 + slot * 16, B + (size_t)row * 512 + boff + g * 8);
        }
    }
    asm volatile("cp.async.commit_group;" ::: "memory");
}

// warp tile 64(m) x 32(n); 8 warps 2x4 over 128x128 CTA tile.
__device__ __forceinline__ void compute_chunk_bf16(
    uint32_t Asm, uint32_t Bsm, float (&acc)[4][4][4], int wm, int wn, int lane)
{
    int j = lane >> 3, rin = lane & 7;
    int jk = j >> 1, jo = (j & 1) * 8;
    int rowA = wm * 64 + jo + rin;
    int rowB = wn * 32 + jo + rin;
    int swA = (rowA >> 1) & 3, swB = (rowB >> 1) & 3;
#pragma unroll
    for (int ks = 0; ks < 2; ks++) {
        uint32_t a[4][4], bb[2][4];
        uint32_t slA = (uint32_t)(((ks * 2 + jk) ^ swA) * 16);
        uint32_t slB = (uint32_t)(((ks * 2 + jk) ^ swB) * 16);
#pragma unroll
        for (int mt = 0; mt < 4; mt++)
            ldm_x4(a[mt], Asm + (rowA + mt * 16) * 64 + slA);
#pragma unroll
        for (int np = 0; np < 2; np++)
            ldm_x4(bb[np], Bsm + (rowB + np * 16) * 64 + slB);
#pragma unroll
        for (int mt = 0; mt < 4; mt++)
#pragma unroll
            for (int nt = 0; nt < 4; nt++)
                mma_bf16(acc[mt][nt], a[mt], bb[nt >> 1][nt & 1], bb[nt >> 1][(nt & 1) + 2]);
    }
}

__device__ __forceinline__ void gemm_bf16(
    const __nv_bfloat16* __restrict__ A, const __nv_bfloat16* __restrict__ B,
    float (&acc)[4][4][4], uint32_t asb, uint32_t bsb, int wm, int wn, int lane)
{
    constexpr int nch = 24;   // 3 passes x 8 chunks
#pragma unroll
    for (int s = 0; s < DEPTH - 1; s++)
        issue_stage_bf16(A, B, s, nch, asb, bsb);
    for (int c = 0; c < nch; c++) {
        asm volatile("cp.async.wait_group 2;" ::: "memory");
        __syncthreads();
        issue_stage_bf16(A, B, c + DEPTH - 1, nch, asb, bsb);
        int buf = c & (DEPTH - 1);
        compute_chunk_bf16(asb + buf * BSTAGE, bsb + buf * BSTAGE, acc, wm, wn, lane);
    }
}

#define BF16_SETUP()                                        \
    extern __shared__ char smem[];                          \
    uint32_t asb = smem_u32(smem);                          \
    uint32_t bsb = asb + DEPTH * BSTAGE;                    \
    int wid = threadIdx.x >> 5, lane = threadIdx.x & 31;    \
    int wm = wid >> 2, wn = wid & 3;                        \
    int gr = lane >> 2, kc = lane & 3;                      \
    float acc[4][4][4];                                     \
    _Pragma("unroll") for (int i = 0; i < 4; i++)           \
    _Pragma("unroll") for (int jj = 0; jj < 4; jj++)        \
    _Pragma("unroll") for (int q = 0; q < 4; q++) acc[i][jj][q] = 0.f;

// ============================ fp32 NN path (ctx only) ==========================
__device__ __forceinline__ void issue_stage_nn(
    const float* __restrict__ A, int lda, const float* __restrict__ B, int ldb,
    int c, int nch, uint32_t asb, uint32_t bsb)
{
    constexpr int kdiv = Mm / BK32;   // 32
    if (c < nch) {
        int kc = c;
        int buf = c & (DEPTH - 1);
        uint32_t ad = asb + buf * (ASTG32 * 4);
        uint32_t bd = bsb + buf * (BSTG_NN * 4);
#pragma unroll
        for (int j = 0; j < 2; j++) {             // A: 128 rows x 4 slots
            int idx = threadIdx.x + 256 * j;
            int row = idx >> 2, slot = idx & 3;
            int g = slot ^ (row & 3);
            cpa16(ad + row * 64 + slot * 16, A + (size_t)row * lda + kc * BK32 + g * 4);
        }
#pragma unroll
        for (int j = 0; j < 2; j++) {             // B: 16 k-rows x 32 segs
            int idx = threadIdx.x + 256 * j;
            int row = idx >> 5, seg = idx & 31;
            cpa16(bd + (row * BNNP + seg * 4) * 4,
                  B + (size_t)(kc * BK32 + row) * ldb + seg * 4);
        }
    }
    asm volatile("cp.async.commit_group;" ::: "memory");
    (void)kdiv;
}

__device__ __forceinline__ void compute_chunk_nn(
    const float* __restrict__ As, const float* __restrict__ Bs,
    float (&acc)[4][4][4], int wm, int wn, int gr, int kc)
{
    const int slot4 = (kc ^ (gr & 3)) * 4;
    uint32_t a[2][4][4], b[2][4][2];
#pragma unroll
    for (int mt = 0; mt < 4; mt++) {
        int r0 = wm * 64 + mt * 16 + gr;
        float4 u = *(const float4*)(As + r0 * BK32 + slot4);
        float4 w = *(const float4*)(As + (r0 + 8) * BK32 + slot4);
        a[0][mt][0] = __float_as_uint(u.x); a[0][mt][1] = __float_as_uint(w.x);
        a[0][mt][2] = __float_as_uint(u.y); a[0][mt][3] = __float_as_uint(w.y);
        a[1][mt][0] = __float_as_uint(u.z); a[1][mt][1] = __float_as_uint(w.z);
        a[1][mt][2] = __float_as_uint(u.w); a[1][mt][3] = __float_as_uint(w.w);
    }
#pragma unroll
    for (int k8 = 0; k8 < 2; k8++)
#pragma unroll
        for (int nt = 0; nt < 4; nt++) {
            const float* p = Bs + (k8 * 8 + kc) * BNNP + wn * 32 + nt * 8 + gr;
            b[k8][nt][0] = __float_as_uint(p[0]);
            b[k8][nt][1] = __float_as_uint(p[4 * BNNP]);
        }
#pragma unroll
    for (int k8 = 0; k8 < 2; k8++)
#pragma unroll
        for (int mt = 0; mt < 4; mt++)
#pragma unroll
            for (int nt = 0; nt < 4; nt++)
                mma_tf32(acc[mt][nt], a[k8][mt], b[k8][nt]);
}

// ---------------- fused split: x/y/W -> bf16 [hi | lo] --------------------------
__global__ void split_all(const float* __restrict__ x, const float* __restrict__ y,
                          const float* __restrict__ Wq, const float* __restrict__ Wk,
                          const float* __restrict__ Wv)
{
    constexpr size_t NX = (size_t)Bb * Mm * Dd;
    constexpr size_t NY = (size_t)BSs * Mm * Dd;
    constexpr size_t NW = (size_t)Dd * Dd;
    size_t i = (size_t)blockIdx.x * blockDim.x + threadIdx.x;
    if (i < NX) {
        int r = (int)(i / Dd), c = (int)(i % Dd);
        float v = x[i];
        __nv_bfloat16 h = __float2bfloat16(v);
        g_x2[(size_t)r * 512 + c] = h;
        g_x2[(size_t)r * 512 + 256 + c] = __float2bfloat16(v - __bfloat162float(h));
    } else if (i < NX + NY) {
        size_t e = i - NX;
        int r = (int)(e / Dd), c = (int)(e % Dd);
        float v = y[e];
        __nv_bfloat16 h = __float2bfloat16(v);
        g_y2[(size_t)r * 512 + c] = h;
        g_y2[(size_t)r * 512 + 256 + c] = __float2bfloat16(v - __bfloat162float(h));
    } else if (i < NX + NY + 3 * NW) {
        size_t j = i - NX - NY;
        int w = (int)(j / NW);
        size_t e = j % NW;
        int r = (int)(e / Dd), c = (int)(e % Dd);
        const float* W = (w == 0) ? Wq : (w == 1) ? Wk : Wv;
        float v = W[e];
        __nv_bfloat16 h = __float2bfloat16(v);
        g_W2[w][(size_t)r * 512 + c] = h;
        g_W2[w][(size_t)r * 512 + 256 + c] = __float2bfloat16(v - __bfloat162float(h));
    }
}

// ---------------- projections (3-pass bf16): z 0..2 x{Q,K,V}, 3..5 y{Q,K,V} -----
__global__ __launch_bounds__(256, 2) void proj_kernel()
{
    int z = blockIdx.z;
    bool isY = z >= 3;
    if (isY && blockIdx.y >= 32) return;
    int mat = z % 3;
    const __nv_bfloat16* A2 = isY ? g_y2 : g_x2;
    const __nv_bfloat16* B2 = g_W2[mat];
    int row0 = blockIdx.y * 128, col0 = blockIdx.x * 128;

    BF16_SETUP();
    gemm_bf16(A2 + (size_t)row0 * 512, B2 + (size_t)col0 * 512,
              acc, asb, bsb, wm, wn, lane);

    if (mat < 2) {
        __nv_bfloat16* Q2 = (mat == 0) ? (isY ? g_Qy2 : g_Qx2) : (isY ? g_Ky2 : g_Kx2);
#pragma unroll
        for (int mt = 0; mt < 4; mt++) {
            int r = row0 + wm * 64 + mt * 16 + gr;
#pragma unroll
            for (int nt = 0; nt < 4; nt++) {
                int c = col0 + wn * 32 + nt * 8 + kc * 2;
#pragma unroll
                for (int h2 = 0; h2 < 2; h2++) {
                    int rr = r + h2 * 8;
                    float v0 = acc[mt][nt][h2 * 2], v1 = acc[mt][nt][h2 * 2 + 1];
                    __nv_bfloat16 h0 = __float2bfloat16(v0);
                    __nv_bfloat16 h1 = __float2bfloat16(v1);
                    __nv_bfloat162 hi; hi.x = h0; hi.y = h1;
                    __nv_bfloat162 lo;
                    lo.x = __float2bfloat16(v0 - __bfloat162float(h0));
                    lo.y = __float2bfloat16(v1 - __bfloat162float(h1));
                    *(__nv_bfloat162*)(Q2 + (size_t)rr * 512 + c) = hi;
                    *(__nv_bfloat162*)(Q2 + (size_t)rr * 512 + 256 + c) = lo;
                }
            }
        }
    } else {
        float* V = isY ? g_Vy : g_Vx;
#pragma unroll
        for (int mt = 0; mt < 4; mt++) {
            int r = row0 + wm * 64 + mt * 16 + gr;
#pragma unroll
            for (int nt = 0; nt < 4; nt++) {
                int c = col0 + wn * 32 + nt * 8 + kc * 2;
#pragma unroll
                for (int h2 = 0; h2 < 2; h2++) {
                    int rr = r + h2 * 8;
                    *(float2*)(V + (size_t)rr * Dd + c) =
                        make_float2(tf32_rna(acc[mt][nt][h2 * 2]),
                                    tf32_rna(acc[mt][nt][h2 * 2 + 1]));
                }
            }
        }
    }
}

// ---------------- masked score GEMMs (3-pass bf16) -------------------------------
template<int MODE>
__global__ __launch_bounds__(256, 2) void scores_kernel(float* __restrict__ outbase)
{
    int zb = blockIdx.z;
    const __nv_bfloat16 *A, *Bp;
    const unsigned char *mr, *mc;
    float* C = outbase + (size_t)zb * Mm * Mm;
    if (MODE == 0) {
        A = g_Qx2 + (size_t)zb * Mm * 512; Bp = g_Kx2 + (size_t)zb * Mm * 512;
        mr = g_mx + zb * Mm; mc = mr;
    } else if (MODE == 1) {
        A = g_Qy2 + (size_t)zb * Mm * 512; Bp = g_Ky2 + (size_t)zb * Mm * 512;
        mr = g_my + zb * Mm; mc = mr;
    } else {
        int n = zb >> 3, s = zb & 7, b = s * 8 + n;
        A = g_Qx2 + (size_t)b * Mm * 512; Bp = g_Ky2 + (size_t)s * Mm * 512;
        mr = g_mx + b * Mm; mc = g_my + s * Mm;
    }
    int row0 = blockIdx.y * 128, col0 = blockIdx.x * 128;

    BF16_SETUP();
    gemm_bf16(A + (size_t)row0 * 512, Bp + (size_t)col0 * 512,
              acc, asb, bsb, wm, wn, lane);

#pragma unroll
    for (int mt = 0; mt < 4; mt++) {
        int r = row0 + wm * 64 + mt * 16 + gr;
        bool rm0 = mr[r] != 0, rm1 = mr[r + 8] != 0;
#pragma unroll
        for (int nt = 0; nt < 4; nt++) {
            int c = col0 + wn * 32 + nt * 8 + kc * 2;
            bool c0 = mc[c] != 0, c1 = mc[c + 1] != 0;
            float2 v0, v1;
            v0.x = (rm0 && c0) ? acc[mt][nt][0] : NEG_FILL_F;
            v0.y = (rm0 && c1) ? acc[mt][nt][1] : NEG_FILL_F;
            v1.x = (rm1 && c0) ? acc[mt][nt][2] : NEG_FILL_F;
            v1.y = (rm1 && c1) ? acc[mt][nt][3] : NEG_FILL_F;
            *(float2*)(C + (size_t)r * Mm + c) = v0;
            *(float2*)(C + (size_t)(r + 8) * Mm + c) = v1;
        }
    }
}

// ---------------- context GEMMs: ctx = P @ V (NN, 1-pass tf32) -------------------
__global__ __launch_bounds__(256, 2) void ctx_kernel(float* __restrict__ out, int which)
{
    extern __shared__ char smemc[];
    float* As = (float*)smemc;
    float* Bs = As + DEPTH * ASTG32;
    int b = blockIdx.z;
    const float* P = (which ? g_Py : g_Px) + (size_t)b * Mm * Mm;
    const float* V = (which ? g_Vy : g_Vx) + (size_t)b * Mm * Dd;
    int row0 = blockIdx.y * 128, col0 = blockIdx.x * 128;

    int wid = threadIdx.x >> 5, lane = threadIdx.x & 31;
    int wm = wid >> 2, wn = wid & 3;
    int gr = lane >> 2, kc = lane & 3;
    float acc[4][4][4];
#pragma unroll
    for (int i = 0; i < 4; i++)
#pragma unroll
        for (int j = 0; j < 4; j++)
#pragma unroll
            for (int q = 0; q < 4; q++) acc[i][j][q] = 0.f;

    const float* Ap = P + (size_t)row0 * Mm;
    const float* Bp = V + col0;
    uint32_t asb = smem_u32(As), bsb = smem_u32(Bs);
    constexpr int nch = Mm / BK32;   // 32
#pragma unroll
    for (int s = 0; s < DEPTH - 1; s++)
        issue_stage_nn(Ap, Mm, Bp, Dd, s, nch, asb, bsb);
    for (int c = 0; c < nch; c++) {
        asm volatile("cp.async.wait_group 2;" ::: "memory");
        __syncthreads();
        issue_stage_nn(Ap, Mm, Bp, Dd, c + DEPTH - 1, nch, asb, bsb);
        int buf = c & (DEPTH - 1);
        compute_chunk_nn(As + buf * ASTG32, Bs + buf * BSTG_NN, acc, wm, wn, gr, kc);
    }

    float* O = out + (size_t)b * Mm * Dd;
#pragma unroll
    for (int mt = 0; mt < 4; mt++) {
        int r = row0 + wm * 64 + mt * 16 + gr;
#pragma unroll
        for (int nt = 0; nt < 4; nt++) {
            int c = col0 + wn * 32 + nt * 8 + kc * 2;
            *(float2*)(O + (size_t)r * Dd + c) =
                make_float2(acc[mt][nt][0], acc[mt][nt][1]);
            *(float2*)(O + (size_t)(r + 8) * Dd + c) =
                make_float2(acc[mt][nt][2], acc[mt][nt][3]);
        }
    }
}

// ---------------- mask normalization (dtype-agnostic) ----------------------------
__global__ void norm_masks_kernel(const unsigned int* __restrict__ mx_in,
                                  const unsigned int* __restrict__ my_in)
{
    const unsigned int* in = (blockIdx.x == 0) ? mx_in : my_in;
    unsigned char* out = (blockIdx.x == 0) ? g_mx : g_my;
    int n = (blockIdx.x == 0) ? Bb * Mm : BSs * Mm;

    __shared__ int s_flag;
    if (threadIdx.x == 0) s_flag = 0;
    __syncthreads();
    int local = 0;
    for (int i = threadIdx.x; i < n / 4; i += blockDim.x)
        if (in[i] > 1u) local = 1;
    if (local) atomicOr(&s_flag, 1);
    __syncthreads();
    bool byte_packed = (s_flag != 0);

    const unsigned char* inb = (const unsigned char*)in;
    for (int i = threadIdx.x; i < n; i += blockDim.x)
        out[i] = byte_packed ? (inb[i] != 0 ? 1 : 0) : (in[i] != 0u ? 1 : 0);
}

// ---------------- row softmax (512 wide) ------------------------------------------
// mode 0/1: tf32-rna probs, sp-permuted, to g_Px/g_Py. mode 2: raw fp32 in place.
__global__ __launch_bounds__(256) void softmax_kernel(
    const float* __restrict__ in, float* __restrict__ outp, int mode)
{
    float* outbase = (mode == 0) ? g_Px : (mode == 1) ? g_Py : outp;
    size_t row = blockIdx.x;
    const float* p = in + row * Mm;
    float* o = outbase + row * Mm;
    int t = threadIdx.x;

    float v0 = p[t];
    float v1 = p[t + 256];
    float m = fmaxf(v0, v1);
#pragma unroll
    for (int off = 16; off; off >>= 1)
        m = fmaxf(m, __shfl_xor_sync(0xffffffffu, m, off));
    __shared__ float smax[8], ssum[8];
    if ((t & 31) == 0) smax[t >> 5] = m;
    __syncthreads();
    float bm = smax[0];
#pragma unroll
    for (int i = 1; i < 8; i++) bm = fmaxf(bm, smax[i]);

    float e0 = __expf(v0 - bm);
    float e1 = __expf(v1 - bm);
    float s = e0 + e1;
#pragma unroll
    for (int off = 16; off; off >>= 1)
        s += __shfl_xor_sync(0xffffffffu, s, off);
    if ((t & 31) == 0) ssum[t >> 5] = s;
    __syncthreads();
    float tot = 0.f;
#pragma unroll
    for (int i = 0; i < 8; i++) tot += ssum[i];
    float inv = 1.0f / tot;
    if (mode < 2) {
        o[sp(t)] = tf32_rna(e0 * inv);
        o[sp(t + 256)] = tf32_rna(e1 * inv);
    } else {
        o[t] = e0 * inv;
        o[t + 256] = e1 * inv;
    }
}

// ---------------- mask_xy as floats, y_len -----------------------------------------
__global__ void mask_xy_kernel(float* __restrict__ out)
{
    int rowid = blockIdx.x;
    int i = rowid & 511;
    int s = (rowid >> 9) & 7;
    int n = rowid >> 12;
    bool rm = g_mx[(s * 8 + n) * Mm + i] != 0;
    float* o = out + (size_t)rowid * Mm;
    for (int j = threadIdx.x; j < Mm; j += blockDim.x)
        o[j] = rm ? (g_my[s * Mm + j] ? 1.0f : 0.0f) : 0.0f;
}

__global__ void ylen_kernel(float* __restrict__ out)
{
    int t = threadIdx.x;
    if (t >= 64) return;
    int s = t & 7;
    int sum = 0;
    for (int j = 0; j < Mm; j++) sum += g_my[s * Mm + j] ? 1 : 0;
    out[t] = (float)sum;
}

// ---------------- launch --------------------------------------------------------------
extern "C" void kernel_launch(void* const* d_in, const int* in_sizes, int n_in,
                              void* d_out, int out_size)
{
    const float* x  = (const float*)d_in[0];
    const float* y  = (const float*)d_in[1];
    const unsigned int* mask_x = (const unsigned int*)d_in[2];
    const unsigned int* mask_y = (const unsigned int*)d_in[3];
    const float* Wq = (const float*)d_in[4];
    const float* Wk = (const float*)d_in[5];
    const float* Wv = (const float*)d_in[6];

    float* out = (float*)d_out;
    float* out_ctx_x = out;                    // 64*512*256
    float* out_ctx_y = out + 8388608;          // 8*512*256
    float* out_sx    = out + 9437184;          // 64*512*512
    float* out_sy    = out + 26214400;         // 8*512*512
    float* out_pxy   = out + 28311552;         // 64*512*512
    float* out_mxy   = out + 45088768;         // 64*512*512
    float* out_ylen  = out + 61865984;         // 64

    cudaFuncSetAttribute(proj_kernel, cudaFuncAttributeMaxDynamicSharedMemorySize, DSMEM_BF);
    cudaFuncSetAttribute(scores_kernel<0>, cudaFuncAttributeMaxDynamicSharedMemorySize, DSMEM_BF);
    cudaFuncSetAttribute(scores_kernel<1>, cudaFuncAttributeMaxDynamicSharedMemorySize, DSMEM_BF);
    cudaFuncSetAttribute(scores_kernel<2>, cudaFuncAttributeMaxDynamicSharedMemorySize, DSMEM_BF);
    cudaFuncSetAttribute(ctx_kernel, cudaFuncAttributeMaxDynamicSharedMemorySize, DSMEM_NN);

    dim3 blk(256);

    norm_masks_kernel<<<2, 1024>>>(mask_x, mask_y);                        // 1
    {
        constexpr size_t TOT = (size_t)Bb * Mm * Dd + (size_t)BSs * Mm * Dd
                             + 3 * (size_t)Dd * Dd;
        split_all<<<(unsigned)((TOT + 255) / 256), 256>>>(x, y, Wq, Wk, Wv); // 2
    }
    proj_kernel<<<dim3(2, 256, 6), blk, DSMEM_BF>>>();                     // 3
    scores_kernel<0><<<dim3(4, 4, 64), blk, DSMEM_BF>>>(out_sx);           // 4 <- profiled
    scores_kernel<2><<<dim3(4, 4, 64), blk, DSMEM_BF>>>(out_pxy);          // 5
    scores_kernel<1><<<dim3(4, 4, 8),  blk, DSMEM_BF>>>(out_sy);           // 6

    softmax_kernel<<<Bb * Mm, 256>>>(out_sx, nullptr, 0);
    softmax_kernel<<<BSs * Mm, 256>>>(out_sy, nullptr, 1);
    softmax_kernel<<<Bb * Mm, 256>>>(out_pxy, out_pxy, 2);

    ctx_kernel<<<dim3(2, 4, 64), blk, DSMEM_NN>>>(out_ctx_x, 0);
    ctx_kernel<<<dim3(2, 4, 8),  blk, DSMEM_NN>>>(out_ctx_y, 1);

    mask_xy_kernel<<<Bb * Mm, 128>>>(out_mxy);
    ylen_kernel<<<1, 64>>>(out_ylen);
}

// round 9
// speedup vs baseline: 2.2959x; 1.0709x over previous
#include <cuda_runtime.h>
#include <cuda_bf16.h>
#include <cstdint>

constexpr int Bb  = 64;
constexpr int BSs = 8;
constexpr int Mm  = 512;
constexpr int Dd  = 256;
constexpr float NEG_FILL_F = -10000000000.0f;

// bf16 NT path: chunk = 64 bf16 k (128B/row), 128 rows -> 16KB per stage side
constexpr int DEPTH_BF = 3;
constexpr int BSTAGE = 16384;                          // bytes per tile stage
constexpr int DSMEM_BF = DEPTH_BF * 2 * BSTAGE;        // 98304 B (96KB)
// fp32 NN path (ctx): BK=16 fp32, DEPTH=4
constexpr int DEPTH_NN = 4;
constexpr int BK32   = 16;
constexpr int BNNP   = 136;
constexpr int ASTG32   = 128 * BK32;                   // floats
constexpr int BSTG_NN  = BK32 * BNNP;                  // floats
constexpr int DSMEM_NN = DEPTH_NN * (ASTG32 + BSTG_NN) * 4;  // 67584 B

// ---------------- scratch ------------------------------------------------------
__device__ __nv_bfloat16 g_x2[(size_t)Bb * Mm * 2 * Dd];   // [hi|lo] width 512
__device__ __nv_bfloat16 g_y2[(size_t)BSs * Mm * 2 * Dd];
__device__ __nv_bfloat16 g_W2[3][(size_t)Dd * 2 * Dd];
__device__ __nv_bfloat16 g_Qx2[(size_t)Bb * Mm * 2 * Dd];
__device__ __nv_bfloat16 g_Kx2[(size_t)Bb * Mm * 2 * Dd];
__device__ __nv_bfloat16 g_Qy2[(size_t)BSs * Mm * 2 * Dd];
__device__ __nv_bfloat16 g_Ky2[(size_t)BSs * Mm * 2 * Dd];
__device__ float g_Vx[(size_t)Bb * Mm * Dd];        // V fp32 tf32-rna
__device__ float g_Vy[(size_t)BSs * Mm * Dd];
__device__ float g_Px[(size_t)Bb * Mm * Mm];        // probs tf32-rna, sp-permuted
__device__ float g_Py[(size_t)BSs * Mm * Mm];
__device__ unsigned char g_mx[Bb * Mm];
__device__ unsigned char g_my[BSs * Mm];

// ---------------- helpers ------------------------------------------------------
__device__ __forceinline__ int sp(int k) {          // involution, used for P only
    return (k & ~15) | ((k & 3) << 2) | ((k >> 2) & 3);
}
__device__ __forceinline__ float tf32_rna(float a) {
    uint32_t o;
    asm("cvt.rna.tf32.f32 %0, %1;" : "=r"(o) : "f"(a));
    return __uint_as_float(o);
}
__device__ __forceinline__ uint32_t smem_u32(const void* p) {
    uint32_t a;
    asm("{ .reg .u64 t; cvta.to.shared.u64 t, %1; cvt.u32.u64 %0, t; }"
        : "=r"(a) : "l"(p));
    return a;
}
__device__ __forceinline__ void cpa16(uint32_t dst, const void* src) {
    asm volatile("cp.async.cg.shared.global [%0], [%1], 16;"
                 :: "r"(dst), "l"(src) : "memory");
}
__device__ __forceinline__ void ldm_x4(uint32_t* r, uint32_t addr) {
    asm volatile("ldmatrix.sync.aligned.m8n8.x4.shared.b16 {%0,%1,%2,%3}, [%4];"
        : "=r"(r[0]), "=r"(r[1]), "=r"(r[2]), "=r"(r[3]) : "r"(addr));
}
__device__ __forceinline__ void mma_bf16(float* c, const uint32_t* a,
                                         uint32_t b0, uint32_t b1) {
    asm volatile(
        "mma.sync.aligned.m16n8k16.row.col.f32.bf16.bf16.f32 "
        "{%0,%1,%2,%3}, {%4,%5,%6,%7}, {%8,%9}, {%0,%1,%2,%3};"
        : "+f"(c[0]), "+f"(c[1]), "+f"(c[2]), "+f"(c[3])
        : "r"(a[0]), "r"(a[1]), "r"(a[2]), "r"(a[3]), "r"(b0), "r"(b1));
}
__device__ __forceinline__ void mma_tf32(float* c, const uint32_t* a, const uint32_t* b) {
    asm volatile(
        "mma.sync.aligned.m16n8k8.row.col.f32.tf32.tf32.f32 "
        "{%0,%1,%2,%3}, {%4,%5,%6,%7}, {%8,%9}, {%0,%1,%2,%3};"
        : "+f"(c[0]), "+f"(c[1]), "+f"(c[2]), "+f"(c[3])
        : "r"(a[0]), "r"(a[1]), "r"(a[2]), "r"(a[3]), "r"(b[0]), "r"(b[1]));
}

// ============================ bf16 NT GEMM path ================================
// smem tile: 128 rows x 128B (64 bf16). Slot swizzle: phys_slot = g ^ (row & 7)
// (8 slots of 16B per row). Conflict-free for cp.async 16B stores (8 lanes/phase
// cover one full row = 32 banks) and ldmatrix phases (8 distinct rows -> 8
// distinct slots -> 32 banks). 3 passes (hi,hi),(lo,hi),(hi,lo).
__device__ __forceinline__ void issue_stage_bf16(
    const __nv_bfloat16* __restrict__ A, const __nv_bfloat16* __restrict__ B,
    int c, int nch, uint32_t asb, uint32_t bsb)
{
    constexpr int kdiv = 4;   // 4 chunks of 64 k per 256-k pass
    if (c < nch) {
        int pass = c / kdiv;
        int kc = c - pass * kdiv;
        int aoff = kc * 64 + ((pass == 1) ? 256 : 0);
        int boff = kc * 64 + ((pass == 2) ? 256 : 0);
        int buf = c % DEPTH_BF;
        uint32_t ad = asb + buf * BSTAGE;
        uint32_t bd = bsb + buf * BSTAGE;
#pragma unroll
        for (int j = 0; j < 4; j++) {             // A: 128 rows x 8 slots
            int idx = threadIdx.x + 256 * j;
            int row = idx >> 3, slot = idx & 7;
            int g = slot ^ (row & 7);
            cpa16(ad + row * 128 + slot * 16, A + (size_t)row * 512 + aoff + g * 8);
        }
#pragma unroll
        for (int j = 0; j < 4; j++) {             // B: 128 rows x 8 slots
            int idx = threadIdx.x + 256 * j;
            int row = idx >> 3, slot = idx & 7;
            int g = slot ^ (row & 7);
            cpa16(bd + row * 128 + slot * 16, B + (size_t)row * 512 + boff + g * 8);
        }
    }
    asm volatile("cp.async.commit_group;" ::: "memory");
}

// warp tile 64(m) x 32(n); 8 warps 2x4 over 128x128 CTA tile; 64 k per chunk.
__device__ __forceinline__ void compute_chunk_bf16(
    uint32_t Asm, uint32_t Bsm, float (&acc)[4][4][4], int wm, int wn, int lane)
{
    int j = lane >> 3, rin = lane & 7;
    int jk = j >> 1, jo = (j & 1) * 8;
    int rowA = wm * 64 + jo + rin;
    int rowB = wn * 32 + jo + rin;
    int swA = rowA & 7, swB = rowB & 7;
#pragma unroll
    for (int ks = 0; ks < 4; ks++) {
        uint32_t a[4][4], bb[2][4];
        uint32_t slA = (uint32_t)(((ks * 2 + jk) ^ swA) * 16);
        uint32_t slB = (uint32_t)(((ks * 2 + jk) ^ swB) * 16);
#pragma unroll
        for (int mt = 0; mt < 4; mt++)
            ldm_x4(a[mt], Asm + (rowA + mt * 16) * 128 + slA);
#pragma unroll
        for (int np = 0; np < 2; np++)
            ldm_x4(bb[np], Bsm + (rowB + np * 16) * 128 + slB);
#pragma unroll
        for (int mt = 0; mt < 4; mt++)
#pragma unroll
            for (int nt = 0; nt < 4; nt++)
                mma_bf16(acc[mt][nt], a[mt], bb[nt >> 1][nt & 1], bb[nt >> 1][(nt & 1) + 2]);
    }
}

__device__ __forceinline__ void gemm_bf16(
    const __nv_bfloat16* __restrict__ A, const __nv_bfloat16* __restrict__ B,
    float (&acc)[4][4][4], uint32_t asb, uint32_t bsb, int wm, int wn, int lane)
{
    constexpr int nch = 12;   // 3 passes x 4 chunks
#pragma unroll
    for (int s = 0; s < DEPTH_BF - 1; s++)
        issue_stage_bf16(A, B, s, nch, asb, bsb);
    for (int c = 0; c < nch; c++) {
        asm volatile("cp.async.wait_group 1;" ::: "memory");
        __syncthreads();
        issue_stage_bf16(A, B, c + DEPTH_BF - 1, nch, asb, bsb);
        int buf = c % DEPTH_BF;
        compute_chunk_bf16(asb + buf * BSTAGE, bsb + buf * BSTAGE, acc, wm, wn, lane);
    }
}

#define BF16_SETUP()                                        \
    extern __shared__ char smem[];                          \
    uint32_t asb = smem_u32(smem);                          \
    uint32_t bsb = asb + DEPTH_BF * BSTAGE;                 \
    int wid = threadIdx.x >> 5, lane = threadIdx.x & 31;    \
    int wm = wid >> 2, wn = wid & 3;                        \
    int gr = lane >> 2, kc = lane & 3;                      \
    float acc[4][4][4];                                     \
    _Pragma("unroll") for (int i = 0; i < 4; i++)           \
    _Pragma("unroll") for (int jj = 0; jj < 4; jj++)        \
    _Pragma("unroll") for (int q = 0; q < 4; q++) acc[i][jj][q] = 0.f;

// ============================ fp32 NN path (ctx only) ==========================
__device__ __forceinline__ void issue_stage_nn(
    const float* __restrict__ A, int lda, const float* __restrict__ B, int ldb,
    int c, int nch, uint32_t asb, uint32_t bsb)
{
    if (c < nch) {
        int kc = c;
        int buf = c & (DEPTH_NN - 1);
        uint32_t ad = asb + buf * (ASTG32 * 4);
        uint32_t bd = bsb + buf * (BSTG_NN * 4);
#pragma unroll
        for (int j = 0; j < 2; j++) {             // A: 128 rows x 4 slots
            int idx = threadIdx.x + 256 * j;
            int row = idx >> 2, slot = idx & 3;
            int g = slot ^ (row & 3);
            cpa16(ad + row * 64 + slot * 16, A + (size_t)row * lda + kc * BK32 + g * 4);
        }
#pragma unroll
        for (int j = 0; j < 2; j++) {             // B: 16 k-rows x 32 segs
            int idx = threadIdx.x + 256 * j;
            int row = idx >> 5, seg = idx & 31;
            cpa16(bd + (row * BNNP + seg * 4) * 4,
                  B + (size_t)(kc * BK32 + row) * ldb + seg * 4);
        }
    }
    asm volatile("cp.async.commit_group;" ::: "memory");
}

__device__ __forceinline__ void compute_chunk_nn(
    const float* __restrict__ As, const float* __restrict__ Bs,
    float (&acc)[4][4][4], int wm, int wn, int gr, int kc)
{
    const int slot4 = (kc ^ (gr & 3)) * 4;
    uint32_t a[2][4][4], b[2][4][2];
#pragma unroll
    for (int mt = 0; mt < 4; mt++) {
        int r0 = wm * 64 + mt * 16 + gr;
        float4 u = *(const float4*)(As + r0 * BK32 + slot4);
        float4 w = *(const float4*)(As + (r0 + 8) * BK32 + slot4);
        a[0][mt][0] = __float_as_uint(u.x); a[0][mt][1] = __float_as_uint(w.x);
        a[0][mt][2] = __float_as_uint(u.y); a[0][mt][3] = __float_as_uint(w.y);
        a[1][mt][0] = __float_as_uint(u.z); a[1][mt][1] = __float_as_uint(w.z);
        a[1][mt][2] = __float_as_uint(u.w); a[1][mt][3] = __float_as_uint(w.w);
    }
#pragma unroll
    for (int k8 = 0; k8 < 2; k8++)
#pragma unroll
        for (int nt = 0; nt < 4; nt++) {
            const float* p = Bs + (k8 * 8 + kc) * BNNP + wn * 32 + nt * 8 + gr;
            b[k8][nt][0] = __float_as_uint(p[0]);
            b[k8][nt][1] = __float_as_uint(p[4 * BNNP]);
        }
#pragma unroll
    for (int k8 = 0; k8 < 2; k8++)
#pragma unroll
        for (int mt = 0; mt < 4; mt++)
#pragma unroll
            for (int nt = 0; nt < 4; nt++)
                mma_tf32(acc[mt][nt], a[k8][mt], b[k8][nt]);
}

// ---------------- fused split: x/y/W -> bf16 [hi | lo] --------------------------
__global__ void split_all(const float* __restrict__ x, const float* __restrict__ y,
                          const float* __restrict__ Wq, const float* __restrict__ Wk,
                          const float* __restrict__ Wv)
{
    constexpr size_t NX = (size_t)Bb * Mm * Dd;
    constexpr size_t NY = (size_t)BSs * Mm * Dd;
    constexpr size_t NW = (size_t)Dd * Dd;
    size_t i = (size_t)blockIdx.x * blockDim.x + threadIdx.x;
    if (i < NX) {
        int r = (int)(i / Dd), c = (int)(i % Dd);
        float v = x[i];
        __nv_bfloat16 h = __float2bfloat16(v);
        g_x2[(size_t)r * 512 + c] = h;
        g_x2[(size_t)r * 512 + 256 + c] = __float2bfloat16(v - __bfloat162float(h));
    } else if (i < NX + NY) {
        size_t e = i - NX;
        int r = (int)(e / Dd), c = (int)(e % Dd);
        float v = y[e];
        __nv_bfloat16 h = __float2bfloat16(v);
        g_y2[(size_t)r * 512 + c] = h;
        g_y2[(size_t)r * 512 + 256 + c] = __float2bfloat16(v - __bfloat162float(h));
    } else if (i < NX + NY + 3 * NW) {
        size_t j = i - NX - NY;
        int w = (int)(j / NW);
        size_t e = j % NW;
        int r = (int)(e / Dd), c = (int)(e % Dd);
        const float* W = (w == 0) ? Wq : (w == 1) ? Wk : Wv;
        float v = W[e];
        __nv_bfloat16 h = __float2bfloat16(v);
        g_W2[w][(size_t)r * 512 + c] = h;
        g_W2[w][(size_t)r * 512 + 256 + c] = __float2bfloat16(v - __bfloat162float(h));
    }
}

// ---------------- projections (3-pass bf16): z 0..2 x{Q,K,V}, 3..5 y{Q,K,V} -----
__global__ __launch_bounds__(256, 2) void proj_kernel()
{
    int z = blockIdx.z;
    bool isY = z >= 3;
    if (isY && blockIdx.y >= 32) return;
    int mat = z % 3;
    const __nv_bfloat16* A2 = isY ? g_y2 : g_x2;
    const __nv_bfloat16* B2 = g_W2[mat];
    int row0 = blockIdx.y * 128, col0 = blockIdx.x * 128;

    BF16_SETUP();
    gemm_bf16(A2 + (size_t)row0 * 512, B2 + (size_t)col0 * 512,
              acc, asb, bsb, wm, wn, lane);

    if (mat < 2) {
        __nv_bfloat16* Q2 = (mat == 0) ? (isY ? g_Qy2 : g_Qx2) : (isY ? g_Ky2 : g_Kx2);
#pragma unroll
        for (int mt = 0; mt < 4; mt++) {
            int r = row0 + wm * 64 + mt * 16 + gr;
#pragma unroll
            for (int nt = 0; nt < 4; nt++) {
                int c = col0 + wn * 32 + nt * 8 + kc * 2;
#pragma unroll
                for (int h2 = 0; h2 < 2; h2++) {
                    int rr = r + h2 * 8;
                    float v0 = acc[mt][nt][h2 * 2], v1 = acc[mt][nt][h2 * 2 + 1];
                    __nv_bfloat16 h0 = __float2bfloat16(v0);
                    __nv_bfloat16 h1 = __float2bfloat16(v1);
                    __nv_bfloat162 hi; hi.x = h0; hi.y = h1;
                    __nv_bfloat162 lo;
                    lo.x = __float2bfloat16(v0 - __bfloat162float(h0));
                    lo.y = __float2bfloat16(v1 - __bfloat162float(h1));
                    *(__nv_bfloat162*)(Q2 + (size_t)rr * 512 + c) = hi;
                    *(__nv_bfloat162*)(Q2 + (size_t)rr * 512 + 256 + c) = lo;
                }
            }
        }
    } else {
        float* V = isY ? g_Vy : g_Vx;
#pragma unroll
        for (int mt = 0; mt < 4; mt++) {
            int r = row0 + wm * 64 + mt * 16 + gr;
#pragma unroll
            for (int nt = 0; nt < 4; nt++) {
                int c = col0 + wn * 32 + nt * 8 + kc * 2;
#pragma unroll
                for (int h2 = 0; h2 < 2; h2++) {
                    int rr = r + h2 * 8;
                    *(float2*)(V + (size_t)rr * Dd + c) =
                        make_float2(tf32_rna(acc[mt][nt][h2 * 2]),
                                    tf32_rna(acc[mt][nt][h2 * 2 + 1]));
                }
            }
        }
    }
}

// ---------------- masked score GEMMs (3-pass bf16) -------------------------------
// MODE 2 additionally writes the float mask_xy output (identical indexing).
template<int MODE>
__global__ __launch_bounds__(256, 2) void scores_kernel(float* __restrict__ outbase,
                                                        float* __restrict__ mxy)
{
    int zb = blockIdx.z;
    const __nv_bfloat16 *A, *Bp;
    const unsigned char *mr, *mc;
    float* C = outbase + (size_t)zb * Mm * Mm;
    float* Mx = (MODE == 2) ? (mxy + (size_t)zb * Mm * Mm) : nullptr;
    if (MODE == 0) {
        A = g_Qx2 + (size_t)zb * Mm * 512; Bp = g_Kx2 + (size_t)zb * Mm * 512;
        mr = g_mx + zb * Mm; mc = mr;
    } else if (MODE == 1) {
        A = g_Qy2 + (size_t)zb * Mm * 512; Bp = g_Ky2 + (size_t)zb * Mm * 512;
        mr = g_my + zb * Mm; mc = mr;
    } else {
        int n = zb >> 3, s = zb & 7, b = s * 8 + n;
        A = g_Qx2 + (size_t)b * Mm * 512; Bp = g_Ky2 + (size_t)s * Mm * 512;
        mr = g_mx + b * Mm; mc = g_my + s * Mm;
    }
    int row0 = blockIdx.y * 128, col0 = blockIdx.x * 128;

    BF16_SETUP();
    gemm_bf16(A + (size_t)row0 * 512, Bp + (size_t)col0 * 512,
              acc, asb, bsb, wm, wn, lane);

#pragma unroll
    for (int mt = 0; mt < 4; mt++) {
        int r = row0 + wm * 64 + mt * 16 + gr;
        bool rm0 = mr[r] != 0, rm1 = mr[r + 8] != 0;
#pragma unroll
        for (int nt = 0; nt < 4; nt++) {
            int c = col0 + wn * 32 + nt * 8 + kc * 2;
            bool c0 = mc[c] != 0, c1 = mc[c + 1] != 0;
            bool m00 = rm0 && c0, m01 = rm0 && c1;
            bool m10 = rm1 && c0, m11 = rm1 && c1;
            float2 v0, v1;
            v0.x = m00 ? acc[mt][nt][0] : NEG_FILL_F;
            v0.y = m01 ? acc[mt][nt][1] : NEG_FILL_F;
            v1.x = m10 ? acc[mt][nt][2] : NEG_FILL_F;
            v1.y = m11 ? acc[mt][nt][3] : NEG_FILL_F;
            *(float2*)(C + (size_t)r * Mm + c) = v0;
            *(float2*)(C + (size_t)(r + 8) * Mm + c) = v1;
            if (MODE == 2) {
                *(float2*)(Mx + (size_t)r * Mm + c) =
                    make_float2(m00 ? 1.f : 0.f, m01 ? 1.f : 0.f);
                *(float2*)(Mx + (size_t)(r + 8) * Mm + c) =
                    make_float2(m10 ? 1.f : 0.f, m11 ? 1.f : 0.f);
            }
        }
    }
}

// ---------------- context GEMMs: ctx = P @ V (NN, 1-pass tf32) -------------------
__global__ __launch_bounds__(256, 2) void ctx_kernel(float* __restrict__ out, int which)
{
    extern __shared__ char smemc[];
    float* As = (float*)smemc;
    float* Bs = As + DEPTH_NN * ASTG32;
    int b = blockIdx.z;
    const float* P = (which ? g_Py : g_Px) + (size_t)b * Mm * Mm;
    const float* V = (which ? g_Vy : g_Vx) + (size_t)b * Mm * Dd;
    int row0 = blockIdx.y * 128, col0 = blockIdx.x * 128;

    int wid = threadIdx.x >> 5, lane = threadIdx.x & 31;
    int wm = wid >> 2, wn = wid & 3;
    int gr = lane >> 2, kc = lane & 3;
    float acc[4][4][4];
#pragma unroll
    for (int i = 0; i < 4; i++)
#pragma unroll
        for (int j = 0; j < 4; j++)
#pragma unroll
            for (int q = 0; q < 4; q++) acc[i][j][q] = 0.f;

    const float* Ap = P + (size_t)row0 * Mm;
    const float* Bp = V + col0;
    uint32_t asb = smem_u32(As), bsb = smem_u32(Bs);
    constexpr int nch = Mm / BK32;   // 32
#pragma unroll
    for (int s = 0; s < DEPTH_NN - 1; s++)
        issue_stage_nn(Ap, Mm, Bp, Dd, s, nch, asb, bsb);
    for (int c = 0; c < nch; c++) {
        asm volatile("cp.async.wait_group 2;" ::: "memory");
        __syncthreads();
        issue_stage_nn(Ap, Mm, Bp, Dd, c + DEPTH_NN - 1, nch, asb, bsb);
        int buf = c & (DEPTH_NN - 1);
        compute_chunk_nn(As + buf * ASTG32, Bs + buf * BSTG_NN, acc, wm, wn, gr, kc);
    }

    float* O = out + (size_t)b * Mm * Dd;
#pragma unroll
    for (int mt = 0; mt < 4; mt++) {
        int r = row0 + wm * 64 + mt * 16 + gr;
#pragma unroll
        for (int nt = 0; nt < 4; nt++) {
            int c = col0 + wn * 32 + nt * 8 + kc * 2;
            *(float2*)(O + (size_t)r * Dd + c) =
                make_float2(acc[mt][nt][0], acc[mt][nt][1]);
            *(float2*)(O + (size_t)(r + 8) * Dd + c) =
                make_float2(acc[mt][nt][2], acc[mt][nt][3]);
        }
    }
}

// ---------------- mask normalization (dtype-agnostic) ----------------------------
__global__ void norm_masks_kernel(const unsigned int* __restrict__ mx_in,
                                  const unsigned int* __restrict__ my_in)
{
    const unsigned int* in = (blockIdx.x == 0) ? mx_in : my_in;
    unsigned char* out = (blockIdx.x == 0) ? g_mx : g_my;
    int n = (blockIdx.x == 0) ? Bb * Mm : BSs * Mm;

    __shared__ int s_flag;
    if (threadIdx.x == 0) s_flag = 0;
    __syncthreads();
    int local = 0;
    for (int i = threadIdx.x; i < n / 4; i += blockDim.x)
        if (in[i] > 1u) local = 1;
    if (local) atomicOr(&s_flag, 1);
    __syncthreads();
    bool byte_packed = (s_flag != 0);

    const unsigned char* inb = (const unsigned char*)in;
    for (int i = threadIdx.x; i < n; i += blockDim.x)
        out[i] = byte_packed ? (inb[i] != 0 ? 1 : 0) : (in[i] != 0u ? 1 : 0);
}

// ---------------- row softmax (512 wide) ------------------------------------------
// mode 0/1: tf32-rna probs, sp-permuted, to g_Px/g_Py. mode 2: raw fp32 in place.
__global__ __launch_bounds__(256) void softmax_kernel(
    const float* __restrict__ in, float* __restrict__ outp, int mode)
{
    float* outbase = (mode == 0) ? g_Px : (mode == 1) ? g_Py : outp;
    size_t row = blockIdx.x;
    const float* p = in + row * Mm;
    float* o = outbase + row * Mm;
    int t = threadIdx.x;

    float v0 = p[t];
    float v1 = p[t + 256];
    float m = fmaxf(v0, v1);
#pragma unroll
    for (int off = 16; off; off >>= 1)
        m = fmaxf(m, __shfl_xor_sync(0xffffffffu, m, off));
    __shared__ float smax[8], ssum[8];
    if ((t & 31) == 0) smax[t >> 5] = m;
    __syncthreads();
    float bm = smax[0];
#pragma unroll
    for (int i = 1; i < 8; i++) bm = fmaxf(bm, smax[i]);

    float e0 = __expf(v0 - bm);
    float e1 = __expf(v1 - bm);
    float s = e0 + e1;
#pragma unroll
    for (int off = 16; off; off >>= 1)
        s += __shfl_xor_sync(0xffffffffu, s, off);
    if ((t & 31) == 0) ssum[t >> 5] = s;
    __syncthreads();
    float tot = 0.f;
#pragma unroll
    for (int i = 0; i < 8; i++) tot += ssum[i];
    float inv = 1.0f / tot;
    if (mode < 2) {
        o[sp(t)] = tf32_rna(e0 * inv);
        o[sp(t + 256)] = tf32_rna(e1 * inv);
    } else {
        o[t] = e0 * inv;
        o[t + 256] = e1 * inv;
    }
}

// ---------------- y_len -------------------------------------------------------------
__global__ void ylen_kernel(float* __restrict__ out)
{
    int t = threadIdx.x;
    if (t >= 64) return;
    int s = t & 7;
    int sum = 0;
    for (int j = 0; j < Mm; j++) sum += g_my[s * Mm + j] ? 1 : 0;
    out[t] = (float)sum;
}

// ---------------- launch --------------------------------------------------------------
extern "C" void kernel_launch(void* const* d_in, const int* in_sizes, int n_in,
                              void* d_out, int out_size)
{
    const float* x  = (const float*)d_in[0];
    const float* y  = (const float*)d_in[1];
    const unsigned int* mask_x = (const unsigned int*)d_in[2];
    const unsigned int* mask_y = (const unsigned int*)d_in[3];
    const float* Wq = (const float*)d_in[4];
    const float* Wk = (const float*)d_in[5];
    const float* Wv = (const float*)d_in[6];

    float* out = (float*)d_out;
    float* out_ctx_x = out;                    // 64*512*256
    float* out_ctx_y = out + 8388608;          // 8*512*256
    float* out_sx    = out + 9437184;          // 64*512*512
    float* out_sy    = out + 26214400;         // 8*512*512
    float* out_pxy   = out + 28311552;         // 64*512*512
    float* out_mxy   = out + 45088768;         // 64*512*512
    float* out_ylen  = out + 61865984;         // 64

    cudaFuncSetAttribute(proj_kernel, cudaFuncAttributeMaxDynamicSharedMemorySize, DSMEM_BF);
    cudaFuncSetAttribute(scores_kernel<0>, cudaFuncAttributeMaxDynamicSharedMemorySize, DSMEM_BF);
    cudaFuncSetAttribute(scores_kernel<1>, cudaFuncAttributeMaxDynamicSharedMemorySize, DSMEM_BF);
    cudaFuncSetAttribute(scores_kernel<2>, cudaFuncAttributeMaxDynamicSharedMemorySize, DSMEM_BF);
    cudaFuncSetAttribute(ctx_kernel, cudaFuncAttributeMaxDynamicSharedMemorySize, DSMEM_NN);

    dim3 blk(256);

    norm_masks_kernel<<<2, 1024>>>(mask_x, mask_y);                          // 1
    {
        constexpr size_t TOT = (size_t)Bb * Mm * Dd + (size_t)BSs * Mm * Dd
                             + 3 * (size_t)Dd * Dd;
        split_all<<<(unsigned)((TOT + 255) / 256), 256>>>(x, y, Wq, Wk, Wv);  // 2
    }
    proj_kernel<<<dim3(2, 256, 6), blk, DSMEM_BF>>>();                       // 3
    scores_kernel<0><<<dim3(4, 4, 64), blk, DSMEM_BF>>>(out_sx, nullptr);    // 4 <- profiled
    scores_kernel<2><<<dim3(4, 4, 64), blk, DSMEM_BF>>>(out_pxy, out_mxy);   // 5
    scores_kernel<1><<<dim3(4, 4, 8),  blk, DSMEM_BF>>>(out_sy, nullptr);    // 6

    softmax_kernel<<<Bb * Mm, 256>>>(out_sx, nullptr, 0);
    softmax_kernel<<<BSs * Mm, 256>>>(out_sy, nullptr, 1);
    softmax_kernel<<<Bb * Mm, 256>>>(out_pxy, out_pxy, 2);

    ctx_kernel<<<dim3(2, 4, 64), blk, DSMEM_NN>>>(out_ctx_x, 0);
    ctx_kernel<<<dim3(2, 4, 8),  blk, DSMEM_NN>>>(out_ctx_y, 1);

    ylen_kernel<<<1, 64>>>(out_ylen);
}